// round 11
// baseline (speedup 1.0000x reference)
#include <cuda_runtime.h>
#include <cuda_bf16.h>
#include <cuda_fp16.h>
#include <math.h>
#include <stdint.h>

#define DIMM   1024
#define HEADS  16
#define HD     64
#define CC     128
#define BSZ    4
#define TLEN   4096
#define NCH    (TLEN/CC)        /* 32 */
#define MTOT   (BSZ*TLEN)       /* 16384 */
#define K2     3072             /* max split K dim (alpha) */
#define NOUT   5120             /* 5 matrices x 1024 */

#define YN  (MTOT*DIMM)
#define SN  (BSZ*HEADS*HD*HD)

// ---------------- scratch ----------------
__device__ float g_q [MTOT*DIMM];           // fp32 q (ymem)
__device__ float g_bt[MTOT*DIMM];           // fp32 softplus(beta) (stats)
__device__ float g_la[MTOT*DIMM];           // log_sigmoid(alpha) (stats)
__device__ __half g_qh[MTOT*DIMM];          // fp16 copies for intra mma
__device__ __half g_kh[MTOT*DIMM];
__device__ __half g_vh[MTOT*DIMM];
__device__ __half g_bh[MTOT*DIMM];
__device__ float g_m [BSZ*NCH*HEADS*CC];
__device__ float g_bm[BSZ*NCH*HEADS*CC];
__device__ __half g_x2[(size_t)MTOT*K2];    // [M,3072] = [hi|lo|hi] fp16
__device__ __half g_w2[(size_t)NOUT*K2];    // qkvb: [hi|-|-]; alpha: [hi|hi|lo]
__device__ float g_delta[(size_t)BSZ*NCH*HEADS*HD*HD];
__device__ float g_stin [(size_t)BSZ*NCH*HEADS*HD*HD];

__device__ __forceinline__ float softplusf(float x) {
    return fmaxf(x, 0.0f) + log1pf(expf(-fabsf(x)));
}
__device__ __forceinline__ uint32_t s2u(const void* p) {
    uint32_t a;
    asm("{ .reg .u64 t; cvta.to.shared.u64 t, %1; cvt.u32.u64 %0, t; }"
        : "=r"(a) : "l"(p));
    return a;
}
__device__ __forceinline__ uint32_t f22h(float a, float b) {
    __half2 h = __floats2half2_rn(a, b);
    return *(uint32_t*)&h;
}
#define CP16(dst,src) asm volatile("cp.async.cg.shared.global [%0], [%1], 16;" ::"r"(dst),"l"(src):"memory")
#define CP_COMMIT()   asm volatile("cp.async.commit_group;" :::"memory")
#define CP_WAIT1()    asm volatile("cp.async.wait_group 1;" :::"memory")

#define LDM_X4(r0,r1,r2,r3,addr) \
    asm volatile("ldmatrix.sync.aligned.m8n8.x4.shared.b16 {%0,%1,%2,%3}, [%4];" \
        : "=r"(r0),"=r"(r1),"=r"(r2),"=r"(r3) : "r"(addr))

#define LDM_X4T(r0,r1,r2,r3,addr) \
    asm volatile("ldmatrix.sync.aligned.m8n8.x4.trans.shared.b16 {%0,%1,%2,%3}, [%4];" \
        : "=r"(r0),"=r"(r1),"=r"(r2),"=r"(r3) : "r"(addr))

#define MMA16816(d0,d1,d2,d3,a0,a1,a2,a3,b0,b1) \
    asm volatile("mma.sync.aligned.m16n8k16.row.col.f32.f16.f16.f32 " \
        "{%0,%1,%2,%3}, {%4,%5,%6,%7}, {%8,%9}, {%0,%1,%2,%3};" \
        : "+f"(d0),"+f"(d1),"+f"(d2),"+f"(d3) \
        : "r"(a0),"r"(a1),"r"(a2),"r"(a3),"r"(b0),"r"(b1))

// ---------------- conversion kernels ----------------
__global__ __launch_bounds__(256) void conv_x_kernel(const float* __restrict__ x)
{
    size_t i4 = (size_t)blockIdx.x * 256 + threadIdx.x;
    float4 v = ((const float4*)x)[i4];
    size_t m = i4 >> 8;
    int k4 = (int)(i4 & 255);
    __half h[4], l[4];
    float vv[4] = {v.x, v.y, v.z, v.w};
    #pragma unroll
    for (int e = 0; e < 4; e++) {
        h[e] = __float2half_rn(vv[e]);
        l[e] = __float2half_rn(vv[e] - __half2float(h[e]));
    }
    __half* dst = g_x2 + m * K2 + k4 * 4;
    *(uint2*)(dst)        = *(uint2*)h;
    *(uint2*)(dst + 1024) = *(uint2*)l;
    *(uint2*)(dst + 2048) = *(uint2*)h;
}

__global__ __launch_bounds__(256) void conv_w_kernel(
    const float* __restrict__ W0, const float* __restrict__ W1,
    const float* __restrict__ W2, const float* __restrict__ W3,
    const float* __restrict__ W4)
{
    size_t i4 = (size_t)blockIdx.x * 256 + threadIdx.x;
    size_t n = i4 >> 8;
    int k4 = (int)(i4 & 255);
    int wsel = (int)(n >> 10);
    const float* W = (wsel == 0) ? W0 : (wsel == 1) ? W1 : (wsel == 2) ? W2
                   : (wsel == 3) ? W3 : W4;
    float4 v = ((const float4*)(W + (n & 1023) * DIMM))[k4];
    __half h[4], l[4];
    float vv[4] = {v.x, v.y, v.z, v.w};
    #pragma unroll
    for (int e = 0; e < 4; e++) {
        h[e] = __float2half_rn(vv[e]);
        l[e] = __float2half_rn(vv[e] - __half2float(h[e]));
    }
    __half* dst = g_w2 + n * K2 + k4 * 4;
    *(uint2*)(dst) = *(uint2*)h;
    if (wsel == 4) {
        *(uint2*)(dst + 1024) = *(uint2*)h;
        *(uint2*)(dst + 2048) = *(uint2*)l;
    }
}

// ---------------- kernel 1: mma.sync fp16 projection GEMM ----------------
// 256x128 block tile, BK=32, 3-stage cp.async, 8 warps (4m x 2n), warp tile 64x64.
// q,k,v,beta: K=1024; alpha: K=3072 split. Alpha blocks launch first (tail balance).
#define BK     32
#define LDS_ROW 80
#define A_TILE_B (256*LDS_ROW)       /* 20480 */
#define B_TILE_B (128*LDS_ROW)       /* 10240 */
#define STG_B    (A_TILE_B + B_TILE_B)
#define PROJ_SMEM (3*STG_B)          /* 92160 */

__global__ __launch_bounds__(256, 1) void proj_mma_kernel(
    const float* __restrict__ bq, const float* __restrict__ bk,
    const float* __restrict__ bv, const float* __restrict__ bb,
    const float* __restrict__ ba, float* __restrict__ alpha_out)
{
    extern __shared__ char dsm[];
    __shared__ float bias_s[128];
    const uint32_t sbase = s2u(dsm);
    const int tid = threadIdx.x;
    const int wid = tid >> 5, lane = tid & 31;
    // alpha-first block ordering
    const int nbid = blockIdx.x;
    const int nb = (nbid < 8) ? (32 + nbid) : (nbid - 8);
    const int mb = blockIdx.y;
    const int wi = nb >> 3;
    const int nkit = (wi == 4) ? (K2 / BK) : (DIMM / BK);
    const int m0 = mb * 256;
    const int r0g = nb * 128;
    const int r0  = (nb & 7) * 128;

    const float* bias = (wi == 0) ? bq : (wi == 1) ? bk : (wi == 2) ? bv
                       : (wi == 3) ? bb : ba;
    if (tid < 128) bias_s[tid] = bias[r0 + tid];

    // ---- load setup: 1536 16B-chunks per stage (A:0..1023, B:1024..1535), 6/thread
    const char* gsrc[6];
    uint32_t    sdst[6];
    #pragma unroll
    for (int j = 0; j < 6; j++) {
        int idx = tid + j * 256;
        if (idx < 1024) {
            int row = idx >> 2, col = idx & 3;
            gsrc[j] = (const char*)(g_x2 + (size_t)(m0 + row) * K2) + col * 16;
            sdst[j] = (uint32_t)row * LDS_ROW + col * 16;
        } else {
            int bidx = idx - 1024;
            int row = bidx >> 2, col = bidx & 3;
            gsrc[j] = (const char*)(g_w2 + (size_t)(r0g + row) * K2) + col * 16;
            sdst[j] = A_TILE_B + (uint32_t)row * LDS_ROW + col * 16;
        }
    }

    #define LOAD_STAGE(s, kit) do {                                     \
        uint32_t st = sbase + (s) * STG_B;                              \
        size_t kb = (size_t)(kit) * (BK * 2);                           \
        _Pragma("unroll")                                               \
        for (int j = 0; j < 6; j++) CP16(st + sdst[j], gsrc[j] + kb);   \
    } while (0)

    // ---- mma fragment addressing: warp tile 64x64
    const int warp_m = wid >> 1;          // 0..3
    const int warp_n = wid & 1;           // 0..1
    const int lr = lane & 15, lh = lane >> 4;
    const uint32_t aOff = (uint32_t)(warp_m * 64 + lr) * LDS_ROW + lh * 16;
    const uint32_t bOff = A_TILE_B + (uint32_t)(warp_n * 64 + lr) * LDS_ROW + lh * 16;

    float acc[4][8][4];
    #pragma unroll
    for (int i = 0; i < 4; i++)
        #pragma unroll
        for (int j = 0; j < 8; j++)
            #pragma unroll
            for (int e = 0; e < 4; e++) acc[i][j][e] = 0.0f;

    LOAD_STAGE(0, 0); CP_COMMIT();
    LOAD_STAGE(1, 1); CP_COMMIT();
    __syncthreads();

    #pragma unroll 1
    for (int i = 0; i < nkit; i++) {
        CP_WAIT1();
        __syncthreads();
        if (i + 2 < nkit) LOAD_STAGE((i + 2) % 3, i + 2);
        CP_COMMIT();

        const uint32_t st = sbase + (i % 3) * STG_B;
        #pragma unroll
        for (int ks = 0; ks < 2; ks++) {
            uint32_t af[4][4];
            #pragma unroll
            for (int mf = 0; mf < 4; mf++)
                LDM_X4(af[mf][0], af[mf][1], af[mf][2], af[mf][3],
                       st + aOff + mf * (16 * LDS_ROW) + ks * 32);
            uint32_t bf[4][4];
            #pragma unroll
            for (int nf = 0; nf < 4; nf++)
                LDM_X4(bf[nf][0], bf[nf][1], bf[nf][2], bf[nf][3],
                       st + bOff + nf * (16 * LDS_ROW) + ks * 32);
            #pragma unroll
            for (int mf = 0; mf < 4; mf++) {
                #pragma unroll
                for (int nf = 0; nf < 4; nf++) {
                    MMA16816(acc[mf][nf*2][0], acc[mf][nf*2][1],
                             acc[mf][nf*2][2], acc[mf][nf*2][3],
                             af[mf][0], af[mf][1], af[mf][2], af[mf][3],
                             bf[nf][0], bf[nf][2]);
                    MMA16816(acc[mf][nf*2+1][0], acc[mf][nf*2+1][1],
                             acc[mf][nf*2+1][2], acc[mf][nf*2+1][3],
                             af[mf][0], af[mf][1], af[mf][2], af[mf][3],
                             bf[nf][1], bf[nf][3]);
                }
            }
        }
    }

    // ---- epilogue
    const int g = lane >> 2, t4 = lane & 3;
    const int mBase = m0 + warp_m * 64;
    #pragma unroll
    for (int mf = 0; mf < 4; mf++) {
        #pragma unroll
        for (int nt = 0; nt < 8; nt++) {
            int nl = warp_n * 64 + nt * 8 + t4 * 2;
            float b0 = bias_s[nl], b1 = bias_s[nl + 1];
            #pragma unroll
            for (int half = 0; half < 2; half++) {
                int m = mBase + mf * 16 + g + half * 8;
                float v0 = acc[mf][nt][half*2 + 0] + b0;
                float v1 = acc[mf][nt][half*2 + 1] + b1;
                size_t off = (size_t)m * DIMM + r0 + nl;
                if (wi == 0) {
                    float s0 = v0 * 0.125f, s1 = v1 * 0.125f;
                    *(float2*)(g_q + off) = make_float2(s0, s1);
                    *(uint32_t*)(g_qh + off) = f22h(s0, s1);
                } else if (wi == 1) {
                    *(uint32_t*)(g_kh + off) = f22h(v0 * 0.125f, v1 * 0.125f);
                } else if (wi == 2) {
                    *(uint32_t*)(g_vh + off) = f22h(v0, v1);
                } else if (wi == 3) {
                    float s0 = softplusf(v0), s1 = softplusf(v1);
                    *(float2*)(g_bt + off) = make_float2(s0, s1);
                    *(uint32_t*)(g_bh + off) = f22h(s0, s1);
                } else {
                    float z0 = fminf(10.0f, fmaxf(-10.0f, v0));
                    float z1 = fminf(10.0f, fmaxf(-10.0f, v1));
                    *(float2*)(alpha_out + off) =
                        make_float2(1.0f/(1.0f+expf(-z0)), 1.0f/(1.0f+expf(-z1)));
                    *(float2*)(g_la + off) =
                        make_float2(-softplusf(-z0), -softplusf(-z1));
                }
            }
        }
    }
}

// ---------------- kernel 2: per-chunk stats ----------------
__global__ __launch_bounds__(128) void stats_kernel()
{
    const int bid = blockIdx.x;
    const int c = threadIdx.x;
    const int h = bid & 15;
    const int n = (bid >> 4) & 31;
    const int b = bid >> 9;
    const int t = b * TLEN + n * CC + c;
    const int base = t * DIMM + h * HD;
    float sla = 0.0f, sb = 0.0f;
    #pragma unroll
    for (int d4 = 0; d4 < HD; d4 += 4) {
        float4 u = *(const float4*)(g_la + base + d4);
        float4 w = *(const float4*)(g_bt + base + d4);
        sla += u.x + u.y + u.z + u.w;
        sb  += w.x + w.y + w.z + w.w;
    }
    g_bm[bid * CC + c] = sb * (1.0f/64.0f);
    __shared__ float smem[CC];
    smem[c] = sla * (1.0f/64.0f);
    __syncthreads();
    #pragma unroll
    for (int off = 1; off < CC; off <<= 1) {
        float prev = (c >= off) ? smem[c - off] : 0.0f;
        __syncthreads();
        smem[c] += prev;
        __syncthreads();
    }
    g_m[bid * CC + c] = smem[c];
}

// ---------------- kernel 3: intra-chunk attention + delta (fp16 mma) ----------------
#define I_QS   0
#define I_KS   (128*72)
#define I_VBT  (2*128*72)
#define I_VBMT (2*128*72 + 64*136)
#define I_HALVES (2*128*72 + 2*64*136)
#define I_BYTES (I_HALVES*2 + 128*4)     /* 72192 */

__global__ __launch_bounds__(256, 1) void intra_kernel(float* __restrict__ y_out)
{
    extern __shared__ __half smh[];
    __half* qs   = smh + I_QS;
    __half* ks   = smh + I_KS;
    __half* vbT  = smh + I_VBT;
    __half* vbmT = smh + I_VBMT;
    float*  ms   = (float*)(smh + I_HALVES);
    const uint32_t qsU = s2u(qs), ksU = s2u(ks);
    const uint32_t vbTU = s2u(vbT), vbmTU = s2u(vbmT);

    const int tid = threadIdx.x;
    const int bid = blockIdx.x;
    const int h = bid & 15;
    const int n = (bid >> 4) & 31;
    const int b = bid >> 9;
    const int tbase = b * TLEN + n * CC;

    #pragma unroll
    for (int it = 0; it < 8; it++) {
        int f  = tid + it * 256;
        int c  = f >> 4;
        int d4 = (f & 15) << 2;
        size_t gi = (size_t)(tbase + c) * DIMM + h * HD + d4;
        *(uint2*)(qs + c*72 + d4) = *(const uint2*)(g_qh + gi);
        *(uint2*)(ks + c*72 + d4) = *(const uint2*)(g_kh + gi);
        uint2 vv = *(const uint2*)(g_vh + gi);
        uint2 bv = *(const uint2*)(g_bh + gi);
        const __half* vh = (const __half*)&vv;
        const __half* bh = (const __half*)&bv;
        float bm = g_bm[bid * CC + c];
        #pragma unroll
        for (int e = 0; e < 4; e++) {
            float vf = __half2float(vh[e]);
            vbT [(d4+e)*136 + c] = __float2half_rn(vf * __half2float(bh[e]));
            vbmT[(d4+e)*136 + c] = __float2half_rn(vf * bm);
        }
    }
    if (tid < 128) ms[tid] = g_m[bid * CC + tid];
    __syncthreads();

    const int w = tid >> 5, lane = tid & 31;
    const int g = lane >> 2, t4 = lane & 3;
    const int lr = lane & 15, lh = lane >> 4;
    const int i0 = w * 16;

    float sacc[16][4];
    #pragma unroll
    for (int j = 0; j < 16; j++)
        #pragma unroll
        for (int e = 0; e < 4; e++) sacc[j][e] = 0.0f;

    #pragma unroll
    for (int ka = 0; ka < 4; ka++) {
        uint32_t a0,a1,a2,a3;
        LDM_X4(a0,a1,a2,a3, qsU + (uint32_t)(i0 + lr)*144 + lh*16 + ka*32);
        #pragma unroll
        for (int jp = 0; jp < 8; jp++) {
            if (jp <= w) {
                uint32_t b0,b1,b2,b3;
                LDM_X4(b0,b1,b2,b3, ksU + (uint32_t)(jp*16 + lr)*144 + lh*16 + ka*32);
                MMA16816(sacc[2*jp][0], sacc[2*jp][1], sacc[2*jp][2], sacc[2*jp][3],
                         a0,a1,a2,a3, b0,b2);
                MMA16816(sacc[2*jp+1][0], sacc[2*jp+1][1], sacc[2*jp+1][2], sacc[2*jp+1][3],
                         a0,a1,a2,a3, b1,b3);
            }
        }
    }

    {
        float mi0 = ms[i0 + g], mi1 = ms[i0 + g + 8];
        int r0 = i0 + g, r1 = i0 + g + 8;
        #pragma unroll
        for (int j = 0; j < 16; j++) {
            if (j <= 2*w + 1) {
                int c0 = j*8 + t4*2, c1 = c0 + 1;
                float mj0 = ms[c0], mj1 = ms[c1];
                sacc[j][0] = (c0 <= r0) ? sacc[j][0] * expf(mi0 - mj0) : 0.0f;
                sacc[j][1] = (c1 <= r0) ? sacc[j][1] * expf(mi0 - mj1) : 0.0f;
                sacc[j][2] = (c0 <= r1) ? sacc[j][2] * expf(mi1 - mj0) : 0.0f;
                sacc[j][3] = (c1 <= r1) ? sacc[j][3] * expf(mi1 - mj1) : 0.0f;
            }
        }
    }

    uint32_t ha[8][4];
    #pragma unroll
    for (int k2 = 0; k2 < 8; k2++) {
        if (k2 <= w) {
            ha[k2][0] = f22h(sacc[2*k2][0],   sacc[2*k2][1]);
            ha[k2][1] = f22h(sacc[2*k2][2],   sacc[2*k2][3]);
            ha[k2][2] = f22h(sacc[2*k2+1][0], sacc[2*k2+1][1]);
            ha[k2][3] = f22h(sacc[2*k2+1][2], sacc[2*k2+1][3]);
        }
    }

    float ya[8][4];
    #pragma unroll
    for (int j = 0; j < 8; j++)
        #pragma unroll
        for (int e = 0; e < 4; e++) ya[j][e] = 0.0f;

    #pragma unroll
    for (int k2 = 0; k2 < 8; k2++) {
        if (k2 <= w) {
            #pragma unroll
            for (int np = 0; np < 4; np++) {
                uint32_t b0,b1,b2,b3;
                LDM_X4(b0,b1,b2,b3, vbTU + (uint32_t)(np*16 + lr)*272 + lh*16 + k2*32);
                MMA16816(ya[2*np][0], ya[2*np][1], ya[2*np][2], ya[2*np][3],
                         ha[k2][0], ha[k2][1], ha[k2][2], ha[k2][3], b0, b2);
                MMA16816(ya[2*np+1][0], ya[2*np+1][1], ya[2*np+1][2], ya[2*np+1][3],
                         ha[k2][0], ha[k2][1], ha[k2][2], ha[k2][3], b1, b3);
            }
        }
    }
    #pragma unroll
    for (int nt = 0; nt < 8; nt++) {
        int dd = nt*8 + t4*2;
        size_t o0 = (size_t)(tbase + i0 + g) * DIMM + h * HD + dd;
        *(float2*)(y_out + o0)            = make_float2(ya[nt][0], ya[nt][1]);
        *(float2*)(y_out + o0 + 8*DIMM)   = make_float2(ya[nt][2], ya[nt][3]);
    }

    {
        const int mt = w >> 1;
        const int nh = w & 1;
        float da[4][4];
        #pragma unroll
        for (int j = 0; j < 4; j++)
            #pragma unroll
            for (int e = 0; e < 4; e++) da[j][e] = 0.0f;

        const int lg = lane >> 3, li = lane & 7;
        const int rowc_off = li + ((lg >> 1) & 1) * 8;
        const int colf = mt*16 + (lg & 1) * 8;
        #pragma unroll
        for (int ka = 0; ka < 8; ka++) {
            uint32_t a0,a1,a2,a3;
            LDM_X4T(a0,a1,a2,a3,
                    ksU + (uint32_t)(ka*16 + rowc_off)*144 + colf*2);
            #pragma unroll
            for (int np = 0; np < 2; np++) {
                uint32_t b0,b1,b2,b3;
                LDM_X4(b0,b1,b2,b3,
                       vbmTU + (uint32_t)(nh*32 + np*16 + lr)*272 + lh*16 + ka*32);
                MMA16816(da[2*np][0], da[2*np][1], da[2*np][2], da[2*np][3],
                         a0,a1,a2,a3, b0,b2);
                MMA16816(da[2*np+1][0], da[2*np+1][1], da[2*np+1][2], da[2*np+1][3],
                         a0,a1,a2,a3, b1,b3);
            }
        }
        size_t dbase = (size_t)bid * 4096;
        #pragma unroll
        for (int nt = 0; nt < 4; nt++) {
            int dd = nh*32 + nt*8 + t4*2;
            int kk = mt*16 + g;
            *(float2*)(g_delta + dbase + (size_t)kk*64 + dd)
                = make_float2(da[nt][0], da[nt][1]);
            *(float2*)(g_delta + dbase + (size_t)(kk+8)*64 + dd)
                = make_float2(da[nt][2], da[nt][3]);
        }
    }
}

// ---------------- kernel 4: state recurrence ----------------
__global__ __launch_bounds__(256) void recur_kernel(float* __restrict__ state_out)
{
    const int bh = blockIdx.x;
    const int b = bh >> 4, h = bh & 15;
    const int tid = threadIdx.x;
    float s[16];
    #pragma unroll
    for (int e = 0; e < 16; e++) s[e] = 0.0f;
    #pragma unroll 1
    for (int n = 0; n < NCH; n++) {
        const int cbid = (b * NCH + n) * HEADS + h;
        float asum = expf(g_m[cbid * CC + (CC - 1)]);
        size_t base = (size_t)cbid * 4096;
        #pragma unroll
        for (int e = 0; e < 16; e++) {
            int idx = tid + e * 256;
            g_stin[base + idx] = s[e];
            s[e] = s[e] * asum + g_delta[base + idx];
        }
    }
    size_t ob = (size_t)bh * 4096;
    #pragma unroll
    for (int e = 0; e < 16; e++) state_out[ob + tid + e * 256] = s[e];
}

// ---------------- kernel 5: y += (q @ state_in) * curve ----------------
__global__ __launch_bounds__(256) void ymem_kernel(float* __restrict__ y_out)
{
    __shared__ float qs[128*68];
    __shared__ float ss[64*68];
    __shared__ float cv[128];
    const int tid = threadIdx.x;
    const int bid = blockIdx.x;
    const int h = bid & 15;
    const int n = (bid >> 4) & 31;
    const int b = bid >> 9;
    const int tb = b * TLEN + n * CC;
    size_t sbase = (size_t)bid * 4096;

    #pragma unroll
    for (int it = 0; it < 8; it++) {
        int f = tid + it * 256;
        int c = f >> 4, d4 = (f & 15) << 2;
        *(float4*)(qs + c*68 + d4) =
            *(const float4*)(g_q + (tb + c) * DIMM + h * HD + d4);
    }
    #pragma unroll
    for (int it = 0; it < 4; it++) {
        int f = tid + it * 256;
        int kk = f >> 4, d4 = (f & 15) << 2;
        *(float4*)(ss + kk*68 + d4) = *(const float4*)(g_stin + sbase + kk*64 + d4);
    }
    if (tid < 128) cv[tid] = expf(g_m[bid * CC + tid]);
    __syncthreads();

    const int tx = tid & 7, ty = tid >> 3;
    const int c0 = ty * 4, dd0 = tx * 8;
    float a0[8], a1[8], a2[8], a3[8];
    #pragma unroll
    for (int e = 0; e < 8; e++) { a0[e]=0.f; a1[e]=0.f; a2[e]=0.f; a3[e]=0.f; }
    #pragma unroll 4
    for (int kk = 0; kk < 64; kk++) {
        float q0 = qs[(c0+0)*68 + kk];
        float q1 = qs[(c0+1)*68 + kk];
        float q2 = qs[(c0+2)*68 + kk];
        float q3 = qs[(c0+3)*68 + kk];
        float sv[8];
        *(float4*)&sv[0] = *(const float4*)&ss[kk*68 + dd0];
        *(float4*)&sv[4] = *(const float4*)&ss[kk*68 + dd0 + 4];
        #pragma unroll
        for (int e = 0; e < 8; e++) {
            a0[e] = fmaf(q0, sv[e], a0[e]);
            a1[e] = fmaf(q1, sv[e], a1[e]);
            a2[e] = fmaf(q2, sv[e], a2[e]);
            a3[e] = fmaf(q3, sv[e], a3[e]);
        }
    }
    #pragma unroll
    for (int i = 0; i < 4; i++) {
        float* ap = (i==0)?a0:(i==1)?a1:(i==2)?a2:a3;
        float cc = cv[c0 + i];
        size_t off = (size_t)(tb + c0 + i) * DIMM + h * HD + dd0;
        float4 o0 = *(float4*)(y_out + off);
        float4 o1 = *(float4*)(y_out + off + 4);
        o0.x += ap[0]*cc; o0.y += ap[1]*cc; o0.z += ap[2]*cc; o0.w += ap[3]*cc;
        o1.x += ap[4]*cc; o1.y += ap[5]*cc; o1.z += ap[6]*cc; o1.w += ap[7]*cc;
        *(float4*)(y_out + off)     = o0;
        *(float4*)(y_out + off + 4) = o1;
    }
}

// ---------------- launch ----------------
extern "C" void kernel_launch(void* const* d_in, const int* in_sizes, int n_in,
                              void* d_out, int out_size)
{
    (void)in_sizes; (void)n_in; (void)out_size;
    const float* x  = (const float*)d_in[0];
    const float* Wq = (const float*)d_in[1];
    const float* bq = (const float*)d_in[2];
    const float* Wk = (const float*)d_in[3];
    const float* bk = (const float*)d_in[4];
    const float* Wv = (const float*)d_in[5];
    const float* bv = (const float*)d_in[6];
    const float* Wb = (const float*)d_in[7];
    const float* bb = (const float*)d_in[8];
    const float* Wa = (const float*)d_in[9];
    const float* ba = (const float*)d_in[10];

    float* out       = (float*)d_out;
    float* y_out     = out;
    float* state_out = out + YN;
    float* alpha_out = out + YN + SN;

    cudaFuncSetAttribute(intra_kernel,
                         cudaFuncAttributeMaxDynamicSharedMemorySize, I_BYTES);
    cudaFuncSetAttribute(proj_mma_kernel,
                         cudaFuncAttributeMaxDynamicSharedMemorySize, PROJ_SMEM);

    conv_x_kernel<<<MTOT * DIMM / 4 / 256, 256>>>(x);
    conv_w_kernel<<<NOUT * DIMM / 4 / 256, 256>>>(Wq, Wk, Wv, Wb, Wa);
    dim3 g1(40, 64);
    proj_mma_kernel<<<g1, 256, PROJ_SMEM>>>(bq, bk, bv, bb, ba, alpha_out);
    stats_kernel<<<BSZ*NCH*HEADS, 128>>>();
    intra_kernel<<<BSZ*NCH*HEADS, 256, I_BYTES>>>(y_out);
    recur_kernel<<<BSZ*HEADS, 256>>>(state_out);
    ymem_kernel<<<BSZ*NCH*HEADS, 256>>>(y_out);
}

// round 12
// speedup vs baseline: 1.1222x; 1.1222x over previous
#include <cuda_runtime.h>
#include <cuda_bf16.h>
#include <cuda_fp16.h>
#include <math.h>
#include <stdint.h>

#define DIMM   1024
#define HEADS  16
#define HD     64
#define CC     128
#define BSZ    4
#define TLEN   4096
#define NCH    (TLEN/CC)        /* 32 */
#define MTOT   (BSZ*TLEN)       /* 16384 */
#define K2     3072             /* max split K dim (alpha) */
#define NOUT   5120             /* 5 matrices x 1024 */

#define YN  (MTOT*DIMM)
#define SN  (BSZ*HEADS*HD*HD)

// ---------------- scratch ----------------
__device__ float g_q [MTOT*DIMM];           // fp32 q (ymem)
__device__ float g_bt[MTOT*DIMM];           // fp32 softplus(beta) (stats)
__device__ float g_la[MTOT*DIMM];           // log_sigmoid(alpha) (stats)
__device__ __half g_qh[MTOT*DIMM];          // fp16 copies for intra mma
__device__ __half g_kh[MTOT*DIMM];
__device__ __half g_vh[MTOT*DIMM];
__device__ __half g_bh[MTOT*DIMM];
__device__ float g_m [BSZ*NCH*HEADS*CC];
__device__ float g_bm[BSZ*NCH*HEADS*CC];
__device__ __half g_x2[(size_t)MTOT*K2];    // [M,3072] = [hi|lo|hi] fp16
__device__ __half g_w2[(size_t)NOUT*K2];    // qkvb: [hi|-|-]; alpha: [hi|hi|lo]
__device__ float g_delta[(size_t)BSZ*NCH*HEADS*HD*HD];
__device__ float g_stin [(size_t)BSZ*NCH*HEADS*HD*HD];

__device__ __forceinline__ float softplusf(float x) {
    return fmaxf(x, 0.0f) + log1pf(expf(-fabsf(x)));
}
__device__ __forceinline__ uint32_t s2u(const void* p) {
    uint32_t a;
    asm("{ .reg .u64 t; cvta.to.shared.u64 t, %1; cvt.u32.u64 %0, t; }"
        : "=r"(a) : "l"(p));
    return a;
}
__device__ __forceinline__ uint32_t f22h(float a, float b) {
    __half2 h = __floats2half2_rn(a, b);
    return *(uint32_t*)&h;
}
#define CP16(dst,src) asm volatile("cp.async.cg.shared.global [%0], [%1], 16;" ::"r"(dst),"l"(src):"memory")
#define CP_COMMIT()   asm volatile("cp.async.commit_group;" :::"memory")
#define CP_WAIT1()    asm volatile("cp.async.wait_group 1;" :::"memory")

#define LDM_X4(r0,r1,r2,r3,addr) \
    asm volatile("ldmatrix.sync.aligned.m8n8.x4.shared.b16 {%0,%1,%2,%3}, [%4];" \
        : "=r"(r0),"=r"(r1),"=r"(r2),"=r"(r3) : "r"(addr))

#define LDM_X4T(r0,r1,r2,r3,addr) \
    asm volatile("ldmatrix.sync.aligned.m8n8.x4.trans.shared.b16 {%0,%1,%2,%3}, [%4];" \
        : "=r"(r0),"=r"(r1),"=r"(r2),"=r"(r3) : "r"(addr))

#define MMA16816(d0,d1,d2,d3,a0,a1,a2,a3,b0,b1) \
    asm volatile("mma.sync.aligned.m16n8k16.row.col.f32.f16.f16.f32 " \
        "{%0,%1,%2,%3}, {%4,%5,%6,%7}, {%8,%9}, {%0,%1,%2,%3};" \
        : "+f"(d0),"+f"(d1),"+f"(d2),"+f"(d3) \
        : "r"(a0),"r"(a1),"r"(a2),"r"(a3),"r"(b0),"r"(b1))

// ---------------- conversion kernels ----------------
__global__ __launch_bounds__(256) void conv_x_kernel(const float* __restrict__ x)
{
    size_t i4 = (size_t)blockIdx.x * 256 + threadIdx.x;
    float4 v = ((const float4*)x)[i4];
    size_t m = i4 >> 8;
    int k4 = (int)(i4 & 255);
    __half h[4], l[4];
    float vv[4] = {v.x, v.y, v.z, v.w};
    #pragma unroll
    for (int e = 0; e < 4; e++) {
        h[e] = __float2half_rn(vv[e]);
        l[e] = __float2half_rn(vv[e] - __half2float(h[e]));
    }
    __half* dst = g_x2 + m * K2 + k4 * 4;
    *(uint2*)(dst)        = *(uint2*)h;
    *(uint2*)(dst + 1024) = *(uint2*)l;
    *(uint2*)(dst + 2048) = *(uint2*)h;
}

__global__ __launch_bounds__(256) void conv_w_kernel(
    const float* __restrict__ W0, const float* __restrict__ W1,
    const float* __restrict__ W2, const float* __restrict__ W3,
    const float* __restrict__ W4)
{
    size_t i4 = (size_t)blockIdx.x * 256 + threadIdx.x;
    size_t n = i4 >> 8;
    int k4 = (int)(i4 & 255);
    int wsel = (int)(n >> 10);
    const float* W = (wsel == 0) ? W0 : (wsel == 1) ? W1 : (wsel == 2) ? W2
                   : (wsel == 3) ? W3 : W4;
    float4 v = ((const float4*)(W + (n & 1023) * DIMM))[k4];
    __half h[4], l[4];
    float vv[4] = {v.x, v.y, v.z, v.w};
    #pragma unroll
    for (int e = 0; e < 4; e++) {
        h[e] = __float2half_rn(vv[e]);
        l[e] = __float2half_rn(vv[e] - __half2float(h[e]));
    }
    __half* dst = g_w2 + n * K2 + k4 * 4;
    *(uint2*)(dst) = *(uint2*)h;
    if (wsel == 4) {
        *(uint2*)(dst + 1024) = *(uint2*)h;
        *(uint2*)(dst + 2048) = *(uint2*)l;
    }
}

// ---------------- kernel 1: mma.sync fp16 projection GEMM ----------------
// q,k,v,beta: K=1024 plain fp16; alpha: K=3072 split [hi|lo|hi]x[hi|hi|lo].
// 128x128 tile, BK=32, 3-stage cp.async, 8 warps (2m x 4n), warp tile 64x32.
// __launch_bounds__(256, 2): cap regs at 128 -> 2 CTAs/SM for latency hiding.
#define BK     32
#define LDS_ROW 80
#define ATILE_B (128*LDS_ROW)
#define STG_B   (2*ATILE_B)
#define PROJ_SMEM (3*STG_B)          /* 61440 */

__global__ __launch_bounds__(256, 2) void proj_mma_kernel(
    const float* __restrict__ bq, const float* __restrict__ bk,
    const float* __restrict__ bv, const float* __restrict__ bb,
    const float* __restrict__ ba, float* __restrict__ alpha_out)
{
    extern __shared__ char dsm[];
    __shared__ float bias_s[128];
    const uint32_t sbase = s2u(dsm);
    const int tid = threadIdx.x;
    const int wid = tid >> 5, lane = tid & 31;
    // alpha-first block ordering (8 long K=3072 blocks launch first)
    const int nbid = blockIdx.x;
    const int nb = (nbid < 8) ? (32 + nbid) : (nbid - 8);
    const int mb = blockIdx.y;
    const int wi = nb >> 3;
    const int nkit = (wi == 4) ? (K2 / BK) : (DIMM / BK);
    const int m0 = mb * 128;
    const int r0g = nb * 128;
    const int r0  = (nb & 7) * 128;

    const float* bias = (wi == 0) ? bq : (wi == 1) ? bk : (wi == 2) ? bv
                       : (wi == 3) ? bb : ba;
    if (tid < 128) bias_s[tid] = bias[r0 + tid];

    int ch0 = tid * 2;
    int arow0 = ch0 >> 2,        ac0 = (ch0 & 3);
    int arow1 = (ch0+1) >> 2,    ac1 = ((ch0+1) & 3);
    const char* aG0 = (const char*)(g_x2 + (size_t)(m0 + arow0) * K2) + ac0 * 16;
    const char* aG1 = (const char*)(g_x2 + (size_t)(m0 + arow1) * K2) + ac1 * 16;
    const char* bG0 = (const char*)(g_w2 + (size_t)(r0g + arow0) * K2) + ac0 * 16;
    const char* bG1 = (const char*)(g_w2 + (size_t)(r0g + arow1) * K2) + ac1 * 16;
    uint32_t aD0 = arow0 * LDS_ROW + ac0 * 16;
    uint32_t aD1 = arow1 * LDS_ROW + ac1 * 16;

    #define LOAD_STAGE(s, kit) do {                                     \
        uint32_t st = sbase + (s) * STG_B;                              \
        size_t kb = (size_t)(kit) * (BK * 2);                           \
        CP16(st + aD0,           aG0 + kb);                             \
        CP16(st + aD1,           aG1 + kb);                             \
        CP16(st + ATILE_B + aD0, bG0 + kb);                             \
        CP16(st + ATILE_B + aD1, bG1 + kb);                             \
    } while (0)

    const int warp_m = wid >> 2;
    const int warp_n = wid & 3;
    const int lr = lane & 15, lh = lane >> 4;
    const uint32_t aOff = (uint32_t)(warp_m * 64 + lr) * LDS_ROW + lh * 16;
    const uint32_t bOff = (uint32_t)(warp_n * 32 + lr) * LDS_ROW + lh * 16 + ATILE_B;

    float acc[4][4][4];
    #pragma unroll
    for (int i = 0; i < 4; i++)
        #pragma unroll
        for (int j = 0; j < 4; j++)
            #pragma unroll
            for (int e = 0; e < 4; e++) acc[i][j][e] = 0.0f;

    LOAD_STAGE(0, 0); CP_COMMIT();
    LOAD_STAGE(1, 1); CP_COMMIT();
    __syncthreads();

    #pragma unroll 1
    for (int i = 0; i < nkit; i++) {
        CP_WAIT1();
        __syncthreads();
        if (i + 2 < nkit) LOAD_STAGE((i + 2) % 3, i + 2);
        CP_COMMIT();

        const uint32_t st = sbase + (i % 3) * STG_B;
        #pragma unroll
        for (int ks = 0; ks < 2; ks++) {
            uint32_t af[4][4];
            #pragma unroll
            for (int mf = 0; mf < 4; mf++)
                LDM_X4(af[mf][0], af[mf][1], af[mf][2], af[mf][3],
                       st + aOff + mf * (16 * LDS_ROW) + ks * 32);
            uint32_t bf[2][4];
            #pragma unroll
            for (int nf = 0; nf < 2; nf++)
                LDM_X4(bf[nf][0], bf[nf][1], bf[nf][2], bf[nf][3],
                       st + bOff + nf * (16 * LDS_ROW) + ks * 32);
            #pragma unroll
            for (int mf = 0; mf < 4; mf++) {
                #pragma unroll
                for (int nf = 0; nf < 2; nf++) {
                    MMA16816(acc[mf][nf*2][0], acc[mf][nf*2][1],
                             acc[mf][nf*2][2], acc[mf][nf*2][3],
                             af[mf][0], af[mf][1], af[mf][2], af[mf][3],
                             bf[nf][0], bf[nf][2]);
                    MMA16816(acc[mf][nf*2+1][0], acc[mf][nf*2+1][1],
                             acc[mf][nf*2+1][2], acc[mf][nf*2+1][3],
                             af[mf][0], af[mf][1], af[mf][2], af[mf][3],
                             bf[nf][1], bf[nf][3]);
                }
            }
        }
    }

    const int g = lane >> 2, t4 = lane & 3;
    const int mBase = m0 + warp_m * 64;
    #pragma unroll
    for (int mf = 0; mf < 4; mf++) {
        #pragma unroll
        for (int nf = 0; nf < 4; nf++) {
            int nl = warp_n * 32 + nf * 8 + t4 * 2;
            float b0 = bias_s[nl], b1 = bias_s[nl + 1];
            #pragma unroll
            for (int half = 0; half < 2; half++) {
                int m = mBase + mf * 16 + g + half * 8;
                float v0 = acc[mf][nf][half*2 + 0] + b0;
                float v1 = acc[mf][nf][half*2 + 1] + b1;
                size_t off = (size_t)m * DIMM + r0 + nl;
                if (wi == 0) {
                    float s0 = v0 * 0.125f, s1 = v1 * 0.125f;
                    *(float2*)(g_q + off) = make_float2(s0, s1);
                    *(uint32_t*)(g_qh + off) = f22h(s0, s1);
                } else if (wi == 1) {
                    *(uint32_t*)(g_kh + off) = f22h(v0 * 0.125f, v1 * 0.125f);
                } else if (wi == 2) {
                    *(uint32_t*)(g_vh + off) = f22h(v0, v1);
                } else if (wi == 3) {
                    float s0 = softplusf(v0), s1 = softplusf(v1);
                    *(float2*)(g_bt + off) = make_float2(s0, s1);
                    *(uint32_t*)(g_bh + off) = f22h(s0, s1);
                } else {
                    float z0 = fminf(10.0f, fmaxf(-10.0f, v0));
                    float z1 = fminf(10.0f, fmaxf(-10.0f, v1));
                    *(float2*)(alpha_out + off) =
                        make_float2(1.0f/(1.0f+expf(-z0)), 1.0f/(1.0f+expf(-z1)));
                    *(float2*)(g_la + off) =
                        make_float2(-softplusf(-z0), -softplusf(-z1));
                }
            }
        }
    }
}

// ---------------- kernel 2: per-chunk stats ----------------
__global__ __launch_bounds__(128) void stats_kernel()
{
    const int bid = blockIdx.x;
    const int c = threadIdx.x;
    const int h = bid & 15;
    const int n = (bid >> 4) & 31;
    const int b = bid >> 9;
    const int t = b * TLEN + n * CC + c;
    const int base = t * DIMM + h * HD;
    float sla = 0.0f, sb = 0.0f;
    #pragma unroll
    for (int d4 = 0; d4 < HD; d4 += 4) {
        float4 u = *(const float4*)(g_la + base + d4);
        float4 w = *(const float4*)(g_bt + base + d4);
        sla += u.x + u.y + u.z + u.w;
        sb  += w.x + w.y + w.z + w.w;
    }
    g_bm[bid * CC + c] = sb * (1.0f/64.0f);
    __shared__ float smem[CC];
    smem[c] = sla * (1.0f/64.0f);
    __syncthreads();
    #pragma unroll
    for (int off = 1; off < CC; off <<= 1) {
        float prev = (c >= off) ? smem[c - off] : 0.0f;
        __syncthreads();
        smem[c] += prev;
        __syncthreads();
    }
    g_m[bid * CC + c] = smem[c];
}

// ---------------- kernel 3: intra-chunk attention + delta (fp16 mma) ----------------
#define I_QS   0
#define I_KS   (128*72)
#define I_VBT  (2*128*72)
#define I_VBMT (2*128*72 + 64*136)
#define I_HALVES (2*128*72 + 2*64*136)
#define I_BYTES (I_HALVES*2 + 128*4)     /* 72192 */

__global__ __launch_bounds__(256, 1) void intra_kernel(float* __restrict__ y_out)
{
    extern __shared__ __half smh[];
    __half* qs   = smh + I_QS;
    __half* ks   = smh + I_KS;
    __half* vbT  = smh + I_VBT;
    __half* vbmT = smh + I_VBMT;
    float*  ms   = (float*)(smh + I_HALVES);
    const uint32_t qsU = s2u(qs), ksU = s2u(ks);
    const uint32_t vbTU = s2u(vbT), vbmTU = s2u(vbmT);

    const int tid = threadIdx.x;
    const int bid = blockIdx.x;
    const int h = bid & 15;
    const int n = (bid >> 4) & 31;
    const int b = bid >> 9;
    const int tbase = b * TLEN + n * CC;

    #pragma unroll
    for (int it = 0; it < 8; it++) {
        int f  = tid + it * 256;
        int c  = f >> 4;
        int d4 = (f & 15) << 2;
        size_t gi = (size_t)(tbase + c) * DIMM + h * HD + d4;
        *(uint2*)(qs + c*72 + d4) = *(const uint2*)(g_qh + gi);
        *(uint2*)(ks + c*72 + d4) = *(const uint2*)(g_kh + gi);
        uint2 vv = *(const uint2*)(g_vh + gi);
        uint2 bv = *(const uint2*)(g_bh + gi);
        const __half* vh = (const __half*)&vv;
        const __half* bh = (const __half*)&bv;
        float bm = g_bm[bid * CC + c];
        #pragma unroll
        for (int e = 0; e < 4; e++) {
            float vf = __half2float(vh[e]);
            vbT [(d4+e)*136 + c] = __float2half_rn(vf * __half2float(bh[e]));
            vbmT[(d4+e)*136 + c] = __float2half_rn(vf * bm);
        }
    }
    if (tid < 128) ms[tid] = g_m[bid * CC + tid];
    __syncthreads();

    const int w = tid >> 5, lane = tid & 31;
    const int g = lane >> 2, t4 = lane & 3;
    const int lr = lane & 15, lh = lane >> 4;
    const int i0 = w * 16;

    float sacc[16][4];
    #pragma unroll
    for (int j = 0; j < 16; j++)
        #pragma unroll
        for (int e = 0; e < 4; e++) sacc[j][e] = 0.0f;

    #pragma unroll
    for (int ka = 0; ka < 4; ka++) {
        uint32_t a0,a1,a2,a3;
        LDM_X4(a0,a1,a2,a3, qsU + (uint32_t)(i0 + lr)*144 + lh*16 + ka*32);
        #pragma unroll
        for (int jp = 0; jp < 8; jp++) {
            if (jp <= w) {
                uint32_t b0,b1,b2,b3;
                LDM_X4(b0,b1,b2,b3, ksU + (uint32_t)(jp*16 + lr)*144 + lh*16 + ka*32);
                MMA16816(sacc[2*jp][0], sacc[2*jp][1], sacc[2*jp][2], sacc[2*jp][3],
                         a0,a1,a2,a3, b0,b2);
                MMA16816(sacc[2*jp+1][0], sacc[2*jp+1][1], sacc[2*jp+1][2], sacc[2*jp+1][3],
                         a0,a1,a2,a3, b1,b3);
            }
        }
    }

    {
        float mi0 = ms[i0 + g], mi1 = ms[i0 + g + 8];
        int r0 = i0 + g, r1 = i0 + g + 8;
        #pragma unroll
        for (int j = 0; j < 16; j++) {
            if (j <= 2*w + 1) {
                int c0 = j*8 + t4*2, c1 = c0 + 1;
                float mj0 = ms[c0], mj1 = ms[c1];
                sacc[j][0] = (c0 <= r0) ? sacc[j][0] * expf(mi0 - mj0) : 0.0f;
                sacc[j][1] = (c1 <= r0) ? sacc[j][1] * expf(mi0 - mj1) : 0.0f;
                sacc[j][2] = (c0 <= r1) ? sacc[j][2] * expf(mi1 - mj0) : 0.0f;
                sacc[j][3] = (c1 <= r1) ? sacc[j][3] * expf(mi1 - mj1) : 0.0f;
            }
        }
    }

    uint32_t ha[8][4];
    #pragma unroll
    for (int k2 = 0; k2 < 8; k2++) {
        if (k2 <= w) {
            ha[k2][0] = f22h(sacc[2*k2][0],   sacc[2*k2][1]);
            ha[k2][1] = f22h(sacc[2*k2][2],   sacc[2*k2][3]);
            ha[k2][2] = f22h(sacc[2*k2+1][0], sacc[2*k2+1][1]);
            ha[k2][3] = f22h(sacc[2*k2+1][2], sacc[2*k2+1][3]);
        }
    }

    float ya[8][4];
    #pragma unroll
    for (int j = 0; j < 8; j++)
        #pragma unroll
        for (int e = 0; e < 4; e++) ya[j][e] = 0.0f;

    #pragma unroll
    for (int k2 = 0; k2 < 8; k2++) {
        if (k2 <= w) {
            #pragma unroll
            for (int np = 0; np < 4; np++) {
                uint32_t b0,b1,b2,b3;
                LDM_X4(b0,b1,b2,b3, vbTU + (uint32_t)(np*16 + lr)*272 + lh*16 + k2*32);
                MMA16816(ya[2*np][0], ya[2*np][1], ya[2*np][2], ya[2*np][3],
                         ha[k2][0], ha[k2][1], ha[k2][2], ha[k2][3], b0, b2);
                MMA16816(ya[2*np+1][0], ya[2*np+1][1], ya[2*np+1][2], ya[2*np+1][3],
                         ha[k2][0], ha[k2][1], ha[k2][2], ha[k2][3], b1, b3);
            }
        }
    }
    #pragma unroll
    for (int nt = 0; nt < 8; nt++) {
        int dd = nt*8 + t4*2;
        size_t o0 = (size_t)(tbase + i0 + g) * DIMM + h * HD + dd;
        *(float2*)(y_out + o0)            = make_float2(ya[nt][0], ya[nt][1]);
        *(float2*)(y_out + o0 + 8*DIMM)   = make_float2(ya[nt][2], ya[nt][3]);
    }

    {
        const int mt = w >> 1;
        const int nh = w & 1;
        float da[4][4];
        #pragma unroll
        for (int j = 0; j < 4; j++)
            #pragma unroll
            for (int e = 0; e < 4; e++) da[j][e] = 0.0f;

        const int lg = lane >> 3, li = lane & 7;
        const int rowc_off = li + ((lg >> 1) & 1) * 8;
        const int colf = mt*16 + (lg & 1) * 8;
        #pragma unroll
        for (int ka = 0; ka < 8; ka++) {
            uint32_t a0,a1,a2,a3;
            LDM_X4T(a0,a1,a2,a3,
                    ksU + (uint32_t)(ka*16 + rowc_off)*144 + colf*2);
            #pragma unroll
            for (int np = 0; np < 2; np++) {
                uint32_t b0,b1,b2,b3;
                LDM_X4(b0,b1,b2,b3,
                       vbmTU + (uint32_t)(nh*32 + np*16 + lr)*272 + lh*16 + ka*32);
                MMA16816(da[2*np][0], da[2*np][1], da[2*np][2], da[2*np][3],
                         a0,a1,a2,a3, b0,b2);
                MMA16816(da[2*np+1][0], da[2*np+1][1], da[2*np+1][2], da[2*np+1][3],
                         a0,a1,a2,a3, b1,b3);
            }
        }
        size_t dbase = (size_t)bid * 4096;
        #pragma unroll
        for (int nt = 0; nt < 4; nt++) {
            int dd = nh*32 + nt*8 + t4*2;
            int kk = mt*16 + g;
            *(float2*)(g_delta + dbase + (size_t)kk*64 + dd)
                = make_float2(da[nt][0], da[nt][1]);
            *(float2*)(g_delta + dbase + (size_t)(kk+8)*64 + dd)
                = make_float2(da[nt][2], da[nt][3]);
        }
    }
}

// ---------------- kernel 4: state recurrence ----------------
__global__ __launch_bounds__(256) void recur_kernel(float* __restrict__ state_out)
{
    const int bh = blockIdx.x;
    const int b = bh >> 4, h = bh & 15;
    const int tid = threadIdx.x;
    float s[16];
    #pragma unroll
    for (int e = 0; e < 16; e++) s[e] = 0.0f;
    #pragma unroll 1
    for (int n = 0; n < NCH; n++) {
        const int cbid = (b * NCH + n) * HEADS + h;
        float asum = expf(g_m[cbid * CC + (CC - 1)]);
        size_t base = (size_t)cbid * 4096;
        #pragma unroll
        for (int e = 0; e < 16; e++) {
            int idx = tid + e * 256;
            g_stin[base + idx] = s[e];
            s[e] = s[e] * asum + g_delta[base + idx];
        }
    }
    size_t ob = (size_t)bh * 4096;
    #pragma unroll
    for (int e = 0; e < 16; e++) state_out[ob + tid + e * 256] = s[e];
}

// ---------------- kernel 5: y += (q @ state_in) * curve ----------------
__global__ __launch_bounds__(256) void ymem_kernel(float* __restrict__ y_out)
{
    __shared__ float qs[128*68];
    __shared__ float ss[64*68];
    __shared__ float cv[128];
    const int tid = threadIdx.x;
    const int bid = blockIdx.x;
    const int h = bid & 15;
    const int n = (bid >> 4) & 31;
    const int b = bid >> 9;
    const int tb = b * TLEN + n * CC;
    size_t sbase = (size_t)bid * 4096;

    #pragma unroll
    for (int it = 0; it < 8; it++) {
        int f = tid + it * 256;
        int c = f >> 4, d4 = (f & 15) << 2;
        *(float4*)(qs + c*68 + d4) =
            *(const float4*)(g_q + (tb + c) * DIMM + h * HD + d4);
    }
    #pragma unroll
    for (int it = 0; it < 4; it++) {
        int f = tid + it * 256;
        int kk = f >> 4, d4 = (f & 15) << 2;
        *(float4*)(ss + kk*68 + d4) = *(const float4*)(g_stin + sbase + kk*64 + d4);
    }
    if (tid < 128) cv[tid] = expf(g_m[bid * CC + tid]);
    __syncthreads();

    const int tx = tid & 7, ty = tid >> 3;
    const int c0 = ty * 4, dd0 = tx * 8;
    float a0[8], a1[8], a2[8], a3[8];
    #pragma unroll
    for (int e = 0; e < 8; e++) { a0[e]=0.f; a1[e]=0.f; a2[e]=0.f; a3[e]=0.f; }
    #pragma unroll 4
    for (int kk = 0; kk < 64; kk++) {
        float q0 = qs[(c0+0)*68 + kk];
        float q1 = qs[(c0+1)*68 + kk];
        float q2 = qs[(c0+2)*68 + kk];
        float q3 = qs[(c0+3)*68 + kk];
        float sv[8];
        *(float4*)&sv[0] = *(const float4*)&ss[kk*68 + dd0];
        *(float4*)&sv[4] = *(const float4*)&ss[kk*68 + dd0 + 4];
        #pragma unroll
        for (int e = 0; e < 8; e++) {
            a0[e] = fmaf(q0, sv[e], a0[e]);
            a1[e] = fmaf(q1, sv[e], a1[e]);
            a2[e] = fmaf(q2, sv[e], a2[e]);
            a3[e] = fmaf(q3, sv[e], a3[e]);
        }
    }
    #pragma unroll
    for (int i = 0; i < 4; i++) {
        float* ap = (i==0)?a0:(i==1)?a1:(i==2)?a2:a3;
        float cc = cv[c0 + i];
        size_t off = (size_t)(tb + c0 + i) * DIMM + h * HD + dd0;
        float4 o0 = *(float4*)(y_out + off);
        float4 o1 = *(float4*)(y_out + off + 4);
        o0.x += ap[0]*cc; o0.y += ap[1]*cc; o0.z += ap[2]*cc; o0.w += ap[3]*cc;
        o1.x += ap[4]*cc; o1.y += ap[5]*cc; o1.z += ap[6]*cc; o1.w += ap[7]*cc;
        *(float4*)(y_out + off)     = o0;
        *(float4*)(y_out + off + 4) = o1;
    }
}

// ---------------- launch ----------------
extern "C" void kernel_launch(void* const* d_in, const int* in_sizes, int n_in,
                              void* d_out, int out_size)
{
    (void)in_sizes; (void)n_in; (void)out_size;
    const float* x  = (const float*)d_in[0];
    const float* Wq = (const float*)d_in[1];
    const float* bq = (const float*)d_in[2];
    const float* Wk = (const float*)d_in[3];
    const float* bk = (const float*)d_in[4];
    const float* Wv = (const float*)d_in[5];
    const float* bv = (const float*)d_in[6];
    const float* Wb = (const float*)d_in[7];
    const float* bb = (const float*)d_in[8];
    const float* Wa = (const float*)d_in[9];
    const float* ba = (const float*)d_in[10];

    float* out       = (float*)d_out;
    float* y_out     = out;
    float* state_out = out + YN;
    float* alpha_out = out + YN + SN;

    cudaFuncSetAttribute(intra_kernel,
                         cudaFuncAttributeMaxDynamicSharedMemorySize, I_BYTES);
    cudaFuncSetAttribute(proj_mma_kernel,
                         cudaFuncAttributeMaxDynamicSharedMemorySize, PROJ_SMEM);

    conv_x_kernel<<<MTOT * DIMM / 4 / 256, 256>>>(x);
    conv_w_kernel<<<NOUT * DIMM / 4 / 256, 256>>>(Wq, Wk, Wv, Wb, Wa);
    dim3 g1(40, 128);
    proj_mma_kernel<<<g1, 256, PROJ_SMEM>>>(bq, bk, bv, bb, ba, alpha_out);
    stats_kernel<<<BSZ*NCH*HEADS, 128>>>();
    intra_kernel<<<BSZ*NCH*HEADS, 256, I_BYTES>>>(y_out);
    recur_kernel<<<BSZ*HEADS, 256>>>(state_out);
    ymem_kernel<<<BSZ*NCH*HEADS, 256>>>(y_out);
}

// round 14
// speedup vs baseline: 1.2005x; 1.0698x over previous
#include <cuda_runtime.h>
#include <cuda_bf16.h>
#include <cuda_fp16.h>
#include <math.h>
#include <stdint.h>

#define DIMM   1024
#define HEADS  16
#define HD     64
#define CC     128
#define BSZ    4
#define TLEN   4096
#define NCH    (TLEN/CC)        /* 32 */
#define MTOT   (BSZ*TLEN)       /* 16384 */
#define K2     3072             /* storage stride (alpha reads 2048) */
#define KA     2048             /* alpha split K (2-term) */
#define NOUT   5120

#define YN  (MTOT*DIMM)
#define SN  (BSZ*HEADS*HD*HD)

// ---------------- scratch ----------------
__device__ float g_q [MTOT*DIMM];
__device__ float g_bt[MTOT*DIMM];
__device__ float g_la[MTOT*DIMM];
__device__ __half g_qh[MTOT*DIMM];
__device__ __half g_kh[MTOT*DIMM];
__device__ __half g_vh[MTOT*DIMM];
__device__ __half g_bh[MTOT*DIMM];
__device__ float g_m [BSZ*NCH*HEADS*CC];
__device__ float g_bm[BSZ*NCH*HEADS*CC];
__device__ __half g_x2[(size_t)MTOT*K2];    // [M,3072] cols 0..2047 = [hi|lo]
__device__ __half g_w2[(size_t)NOUT*K2];    // qkvb: [hi]; alpha: [hi|hi]
__device__ float g_delta[(size_t)BSZ*NCH*HEADS*HD*HD];
__device__ float g_stin [(size_t)BSZ*NCH*HEADS*HD*HD];

__device__ __forceinline__ float softplusf(float x) {
    return fmaxf(x, 0.0f) + log1pf(expf(-fabsf(x)));
}
__device__ __forceinline__ uint32_t s2u(const void* p) {
    uint32_t a;
    asm("{ .reg .u64 t; cvta.to.shared.u64 t, %1; cvt.u32.u64 %0, t; }"
        : "=r"(a) : "l"(p));
    return a;
}
__device__ __forceinline__ uint32_t f22h(float a, float b) {
    __half2 h = __floats2half2_rn(a, b);
    return *(uint32_t*)&h;
}
#define CP16(dst,src) asm volatile("cp.async.cg.shared.global [%0], [%1], 16;" ::"r"(dst),"l"(src):"memory")
#define CP_COMMIT()   asm volatile("cp.async.commit_group;" :::"memory")
#define CP_WAITN(n)   asm volatile("cp.async.wait_group %0;" ::"n"(n):"memory")

#define LDM_X4(r0,r1,r2,r3,addr) \
    asm volatile("ldmatrix.sync.aligned.m8n8.x4.shared.b16 {%0,%1,%2,%3}, [%4];" \
        : "=r"(r0),"=r"(r1),"=r"(r2),"=r"(r3) : "r"(addr))

#define LDM_X4T(r0,r1,r2,r3,addr) \
    asm volatile("ldmatrix.sync.aligned.m8n8.x4.trans.shared.b16 {%0,%1,%2,%3}, [%4];" \
        : "=r"(r0),"=r"(r1),"=r"(r2),"=r"(r3) : "r"(addr))

#define MMA16816(d0,d1,d2,d3,a0,a1,a2,a3,b0,b1) \
    asm volatile("mma.sync.aligned.m16n8k16.row.col.f32.f16.f16.f32 " \
        "{%0,%1,%2,%3}, {%4,%5,%6,%7}, {%8,%9}, {%0,%1,%2,%3};" \
        : "+f"(d0),"+f"(d1),"+f"(d2),"+f"(d3) \
        : "r"(a0),"r"(a1),"r"(a2),"r"(a3),"r"(b0),"r"(b1))

// ---------------- conversion kernels ----------------
__global__ __launch_bounds__(256) void conv_x_kernel(const float* __restrict__ x)
{
    size_t i4 = (size_t)blockIdx.x * 256 + threadIdx.x;
    float4 v = ((const float4*)x)[i4];
    size_t m = i4 >> 8;
    int k4 = (int)(i4 & 255);
    __half h[4], l[4];
    float vv[4] = {v.x, v.y, v.z, v.w};
    #pragma unroll
    for (int e = 0; e < 4; e++) {
        h[e] = __float2half_rn(vv[e]);
        l[e] = __float2half_rn(vv[e] - __half2float(h[e]));
    }
    __half* dst = g_x2 + m * K2 + k4 * 4;
    *(uint2*)(dst)        = *(uint2*)h;
    *(uint2*)(dst + 1024) = *(uint2*)l;
}

__global__ __launch_bounds__(256) void conv_w_kernel(
    const float* __restrict__ W0, const float* __restrict__ W1,
    const float* __restrict__ W2, const float* __restrict__ W3,
    const float* __restrict__ W4)
{
    size_t i4 = (size_t)blockIdx.x * 256 + threadIdx.x;
    size_t n = i4 >> 8;
    int k4 = (int)(i4 & 255);
    int wsel = (int)(n >> 10);
    const float* W = (wsel == 0) ? W0 : (wsel == 1) ? W1 : (wsel == 2) ? W2
                   : (wsel == 3) ? W3 : W4;
    float4 v = ((const float4*)(W + (n & 1023) * DIMM))[k4];
    __half h[4];
    float vv[4] = {v.x, v.y, v.z, v.w};
    #pragma unroll
    for (int e = 0; e < 4; e++) h[e] = __float2half_rn(vv[e]);
    __half* dst = g_w2 + n * K2 + k4 * 4;
    *(uint2*)(dst) = *(uint2*)h;
    if (wsel == 4) *(uint2*)(dst + 1024) = *(uint2*)h;   // alpha: w = [hi|hi]
}

// ---------------- kernel 1: mma.sync fp16 projection GEMM ----------------
// q,k,v,beta: K=1024 fp16 hi; alpha: K=2048 2-term ([hi|lo] x [hi|hi] = x·w_hi).
// 128x128 tile, BK=32, 4-stage cp.async, 8 warps (2m x 4n), warp tile 64x32.
#define BK     32
#define LDS_ROW 80
#define ATILE_B (128*LDS_ROW)
#define STG_B   (2*ATILE_B)
#define NSTG   4
#define PROJ_SMEM (NSTG*STG_B)       /* 81920 */

__global__ __launch_bounds__(256, 2) void proj_mma_kernel(
    const float* __restrict__ bq, const float* __restrict__ bk,
    const float* __restrict__ bv, const float* __restrict__ bb,
    const float* __restrict__ ba, float* __restrict__ alpha_out)
{
    extern __shared__ char dsm[];
    __shared__ float bias_s[128];
    const uint32_t sbase = s2u(dsm);
    const int tid = threadIdx.x;
    const int wid = tid >> 5, lane = tid & 31;
    // alpha-first block ordering (8 long K=2048 blocks launch first)
    const int nbid = blockIdx.x;
    const int nb = (nbid < 8) ? (32 + nbid) : (nbid - 8);
    const int mb = blockIdx.y;
    const int wi = nb >> 3;
    const int nkit = (wi == 4) ? (KA / BK) : (DIMM / BK);   // 64 or 32
    const int m0 = mb * 128;
    const int r0g = nb * 128;
    const int r0  = (nb & 7) * 128;

    const float* bias = (wi == 0) ? bq : (wi == 1) ? bk : (wi == 2) ? bv
                       : (wi == 3) ? bb : ba;
    if (tid < 128) bias_s[tid] = bias[r0 + tid];

    int ch0 = tid * 2;
    int arow0 = ch0 >> 2,        ac0 = (ch0 & 3);
    int arow1 = (ch0+1) >> 2,    ac1 = ((ch0+1) & 3);
    const char* aG0 = (const char*)(g_x2 + (size_t)(m0 + arow0) * K2) + ac0 * 16;
    const char* aG1 = (const char*)(g_x2 + (size_t)(m0 + arow1) * K2) + ac1 * 16;
    const char* bG0 = (const char*)(g_w2 + (size_t)(r0g + arow0) * K2) + ac0 * 16;
    const char* bG1 = (const char*)(g_w2 + (size_t)(r0g + arow1) * K2) + ac1 * 16;
    uint32_t aD0 = arow0 * LDS_ROW + ac0 * 16;
    uint32_t aD1 = arow1 * LDS_ROW + ac1 * 16;

    #define LOAD_STAGE(s, kit) do {                                     \
        uint32_t st = sbase + (s) * STG_B;                              \
        size_t kb = (size_t)(kit) * (BK * 2);                           \
        CP16(st + aD0,           aG0 + kb);                             \
        CP16(st + aD1,           aG1 + kb);                             \
        CP16(st + ATILE_B + aD0, bG0 + kb);                             \
        CP16(st + ATILE_B + aD1, bG1 + kb);                             \
        CP_COMMIT();                                                    \
    } while (0)

    const int warp_m = wid >> 2;
    const int warp_n = wid & 3;
    const int lr = lane & 15, lh = lane >> 4;
    const uint32_t aOff = (uint32_t)(warp_m * 64 + lr) * LDS_ROW + lh * 16;
    const uint32_t bOff = (uint32_t)(warp_n * 32 + lr) * LDS_ROW + lh * 16 + ATILE_B;

    float acc[4][4][4];
    #pragma unroll
    for (int i = 0; i < 4; i++)
        #pragma unroll
        for (int j = 0; j < 4; j++)
            #pragma unroll
            for (int e = 0; e < 4; e++) acc[i][j][e] = 0.0f;

    LOAD_STAGE(0, 0);
    LOAD_STAGE(1, 1);
    LOAD_STAGE(2, 2);
    __syncthreads();

    #pragma unroll 1
    for (int i = 0; i < nkit; i++) {
        if      (i + 2 < nkit) CP_WAITN(2);
        else if (i + 1 < nkit) CP_WAITN(1);
        else                   CP_WAITN(0);
        __syncthreads();
        if (i + 3 < nkit) LOAD_STAGE((i + 3) % NSTG, i + 3);

        const uint32_t st = sbase + (i % NSTG) * STG_B;
        #pragma unroll
        for (int ks = 0; ks < 2; ks++) {
            uint32_t af[4][4];
            #pragma unroll
            for (int mf = 0; mf < 4; mf++)
                LDM_X4(af[mf][0], af[mf][1], af[mf][2], af[mf][3],
                       st + aOff + mf * (16 * LDS_ROW) + ks * 32);
            uint32_t bf[2][4];
            #pragma unroll
            for (int nf = 0; nf < 2; nf++)
                LDM_X4(bf[nf][0], bf[nf][1], bf[nf][2], bf[nf][3],
                       st + bOff + nf * (16 * LDS_ROW) + ks * 32);
            #pragma unroll
            for (int mf = 0; mf < 4; mf++) {
                #pragma unroll
                for (int nf = 0; nf < 2; nf++) {
                    MMA16816(acc[mf][nf*2][0], acc[mf][nf*2][1],
                             acc[mf][nf*2][2], acc[mf][nf*2][3],
                             af[mf][0], af[mf][1], af[mf][2], af[mf][3],
                             bf[nf][0], bf[nf][2]);
                    MMA16816(acc[mf][nf*2+1][0], acc[mf][nf*2+1][1],
                             acc[mf][nf*2+1][2], acc[mf][nf*2+1][3],
                             af[mf][0], af[mf][1], af[mf][2], af[mf][3],
                             bf[nf][1], bf[nf][3]);
                }
            }
        }
    }

    const int g = lane >> 2, t4 = lane & 3;
    const int mBase = m0 + warp_m * 64;
    #pragma unroll
    for (int mf = 0; mf < 4; mf++) {
        #pragma unroll
        for (int nf = 0; nf < 4; nf++) {
            int nl = warp_n * 32 + nf * 8 + t4 * 2;
            float b0 = bias_s[nl], b1 = bias_s[nl + 1];
            #pragma unroll
            for (int half = 0; half < 2; half++) {
                int m = mBase + mf * 16 + g + half * 8;
                float v0 = acc[mf][nf][half*2 + 0] + b0;
                float v1 = acc[mf][nf][half*2 + 1] + b1;
                size_t off = (size_t)m * DIMM + r0 + nl;
                if (wi == 0) {
                    float s0 = v0 * 0.125f, s1 = v1 * 0.125f;
                    *(float2*)(g_q + off) = make_float2(s0, s1);
                    *(uint32_t*)(g_qh + off) = f22h(s0, s1);
                } else if (wi == 1) {
                    *(uint32_t*)(g_kh + off) = f22h(v0 * 0.125f, v1 * 0.125f);
                } else if (wi == 2) {
                    *(uint32_t*)(g_vh + off) = f22h(v0, v1);
                } else if (wi == 3) {
                    float s0 = softplusf(v0), s1 = softplusf(v1);
                    *(float2*)(g_bt + off) = make_float2(s0, s1);
                    *(uint32_t*)(g_bh + off) = f22h(s0, s1);
                } else {
                    float z0 = fminf(10.0f, fmaxf(-10.0f, v0));
                    float z1 = fminf(10.0f, fmaxf(-10.0f, v1));
                    *(float2*)(alpha_out + off) =
                        make_float2(1.0f/(1.0f+expf(-z0)), 1.0f/(1.0f+expf(-z1)));
                    *(float2*)(g_la + off) =
                        make_float2(-softplusf(-z0), -softplusf(-z1));
                }
            }
        }
    }
}

// ---------------- kernel 2: per-chunk stats ----------------
__global__ __launch_bounds__(128) void stats_kernel()
{
    const int bid = blockIdx.x;
    const int c = threadIdx.x;
    const int h = bid & 15;
    const int n = (bid >> 4) & 31;
    const int b = bid >> 9;
    const int t = b * TLEN + n * CC + c;
    const int base = t * DIMM + h * HD;
    float sla = 0.0f, sb = 0.0f;
    #pragma unroll
    for (int d4 = 0; d4 < HD; d4 += 4) {
        float4 u = *(const float4*)(g_la + base + d4);
        float4 w = *(const float4*)(g_bt + base + d4);
        sla += u.x + u.y + u.z + u.w;
        sb  += w.x + w.y + w.z + w.w;
    }
    g_bm[bid * CC + c] = sb * (1.0f/64.0f);
    __shared__ float smem[CC];
    smem[c] = sla * (1.0f/64.0f);
    __syncthreads();
    #pragma unroll
    for (int off = 1; off < CC; off <<= 1) {
        float prev = (c >= off) ? smem[c - off] : 0.0f;
        __syncthreads();
        smem[c] += prev;
        __syncthreads();
    }
    g_m[bid * CC + c] = smem[c];
}

// ---------------- kernel 3: intra-chunk attention + delta (fp16 mma) ----------------
#define I_QS   0
#define I_KS   (128*72)
#define I_VBT  (2*128*72)
#define I_VBMT (2*128*72 + 64*136)
#define I_HALVES (2*128*72 + 2*64*136)
#define I_BYTES (I_HALVES*2 + 128*4)     /* 72192 */

__global__ __launch_bounds__(256, 1) void intra_kernel(float* __restrict__ y_out)
{
    extern __shared__ __half smh[];
    __half* qs   = smh + I_QS;
    __half* ks   = smh + I_KS;
    __half* vbT  = smh + I_VBT;
    __half* vbmT = smh + I_VBMT;
    float*  ms   = (float*)(smh + I_HALVES);
    const uint32_t qsU = s2u(qs), ksU = s2u(ks);
    const uint32_t vbTU = s2u(vbT), vbmTU = s2u(vbmT);

    const int tid = threadIdx.x;
    const int bid = blockIdx.x;
    const int h = bid & 15;
    const int n = (bid >> 4) & 31;
    const int b = bid >> 9;
    const int tbase = b * TLEN + n * CC;

    #pragma unroll
    for (int it = 0; it < 8; it++) {
        int f  = tid + it * 256;
        int c  = f >> 4;
        int d4 = (f & 15) << 2;
        size_t gi = (size_t)(tbase + c) * DIMM + h * HD + d4;
        *(uint2*)(qs + c*72 + d4) = *(const uint2*)(g_qh + gi);
        *(uint2*)(ks + c*72 + d4) = *(const uint2*)(g_kh + gi);
        uint2 vv = *(const uint2*)(g_vh + gi);
        uint2 bv = *(const uint2*)(g_bh + gi);
        const __half* vh = (const __half*)&vv;
        const __half* bh = (const __half*)&bv;
        float bm = g_bm[bid * CC + c];
        #pragma unroll
        for (int e = 0; e < 4; e++) {
            float vf = __half2float(vh[e]);
            vbT [(d4+e)*136 + c] = __float2half_rn(vf * __half2float(bh[e]));
            vbmT[(d4+e)*136 + c] = __float2half_rn(vf * bm);
        }
    }
    if (tid < 128) ms[tid] = g_m[bid * CC + tid];
    __syncthreads();

    const int w = tid >> 5, lane = tid & 31;
    const int g = lane >> 2, t4 = lane & 3;
    const int lr = lane & 15, lh = lane >> 4;
    const int i0 = w * 16;

    float sacc[16][4];
    #pragma unroll
    for (int j = 0; j < 16; j++)
        #pragma unroll
        for (int e = 0; e < 4; e++) sacc[j][e] = 0.0f;

    #pragma unroll
    for (int ka = 0; ka < 4; ka++) {
        uint32_t a0,a1,a2,a3;
        LDM_X4(a0,a1,a2,a3, qsU + (uint32_t)(i0 + lr)*144 + lh*16 + ka*32);
        #pragma unroll
        for (int jp = 0; jp < 8; jp++) {
            if (jp <= w) {
                uint32_t b0,b1,b2,b3;
                LDM_X4(b0,b1,b2,b3, ksU + (uint32_t)(jp*16 + lr)*144 + lh*16 + ka*32);
                MMA16816(sacc[2*jp][0], sacc[2*jp][1], sacc[2*jp][2], sacc[2*jp][3],
                         a0,a1,a2,a3, b0,b2);
                MMA16816(sacc[2*jp+1][0], sacc[2*jp+1][1], sacc[2*jp+1][2], sacc[2*jp+1][3],
                         a0,a1,a2,a3, b1,b3);
            }
        }
    }

    {
        float mi0 = ms[i0 + g], mi1 = ms[i0 + g + 8];
        int r0 = i0 + g, r1 = i0 + g + 8;
        #pragma unroll
        for (int j = 0; j < 16; j++) {
            if (j <= 2*w + 1) {
                int c0 = j*8 + t4*2, c1 = c0 + 1;
                float mj0 = ms[c0], mj1 = ms[c1];
                sacc[j][0] = (c0 <= r0) ? sacc[j][0] * expf(mi0 - mj0) : 0.0f;
                sacc[j][1] = (c1 <= r0) ? sacc[j][1] * expf(mi0 - mj1) : 0.0f;
                sacc[j][2] = (c0 <= r1) ? sacc[j][2] * expf(mi1 - mj0) : 0.0f;
                sacc[j][3] = (c1 <= r1) ? sacc[j][3] * expf(mi1 - mj1) : 0.0f;
            }
        }
    }

    uint32_t ha[8][4];
    #pragma unroll
    for (int k2 = 0; k2 < 8; k2++) {
        if (k2 <= w) {
            ha[k2][0] = f22h(sacc[2*k2][0],   sacc[2*k2][1]);
            ha[k2][1] = f22h(sacc[2*k2][2],   sacc[2*k2][3]);
            ha[k2][2] = f22h(sacc[2*k2+1][0], sacc[2*k2+1][1]);
            ha[k2][3] = f22h(sacc[2*k2+1][2], sacc[2*k2+1][3]);
        }
    }

    float ya[8][4];
    #pragma unroll
    for (int j = 0; j < 8; j++)
        #pragma unroll
        for (int e = 0; e < 4; e++) ya[j][e] = 0.0f;

    #pragma unroll
    for (int k2 = 0; k2 < 8; k2++) {
        if (k2 <= w) {
            #pragma unroll
            for (int np = 0; np < 4; np++) {
                uint32_t b0,b1,b2,b3;
                LDM_X4(b0,b1,b2,b3, vbTU + (uint32_t)(np*16 + lr)*272 + lh*16 + k2*32);
                MMA16816(ya[2*np][0], ya[2*np][1], ya[2*np][2], ya[2*np][3],
                         ha[k2][0], ha[k2][1], ha[k2][2], ha[k2][3], b0, b2);
                MMA16816(ya[2*np+1][0], ya[2*np+1][1], ya[2*np+1][2], ya[2*np+1][3],
                         ha[k2][0], ha[k2][1], ha[k2][2], ha[k2][3], b1, b3);
            }
        }
    }
    #pragma unroll
    for (int nt = 0; nt < 8; nt++) {
        int dd = nt*8 + t4*2;
        size_t o0 = (size_t)(tbase + i0 + g) * DIMM + h * HD + dd;
        *(float2*)(y_out + o0)            = make_float2(ya[nt][0], ya[nt][1]);
        *(float2*)(y_out + o0 + 8*DIMM)   = make_float2(ya[nt][2], ya[nt][3]);
    }

    {
        const int mt = w >> 1;
        const int nh = w & 1;
        float da[4][4];
        #pragma unroll
        for (int j = 0; j < 4; j++)
            #pragma unroll
            for (int e = 0; e < 4; e++) da[j][e] = 0.0f;

        const int lg = lane >> 3, li = lane & 7;
        const int rowc_off = li + ((lg >> 1) & 1) * 8;
        const int colf = mt*16 + (lg & 1) * 8;
        #pragma unroll
        for (int ka = 0; ka < 8; ka++) {
            uint32_t a0,a1,a2,a3;
            LDM_X4T(a0,a1,a2,a3,
                    ksU + (uint32_t)(ka*16 + rowc_off)*144 + colf*2);
            #pragma unroll
            for (int np = 0; np < 2; np++) {
                uint32_t b0,b1,b2,b3;
                LDM_X4(b0,b1,b2,b3,
                       vbmTU + (uint32_t)(nh*32 + np*16 + lr)*272 + lh*16 + ka*32);
                MMA16816(da[2*np][0], da[2*np][1], da[2*np][2], da[2*np][3],
                         a0,a1,a2,a3, b0,b2);
                MMA16816(da[2*np+1][0], da[2*np+1][1], da[2*np+1][2], da[2*np+1][3],
                         a0,a1,a2,a3, b1,b3);
            }
        }
        size_t dbase = (size_t)bid * 4096;
        #pragma unroll
        for (int nt = 0; nt < 4; nt++) {
            int dd = nh*32 + nt*8 + t4*2;
            int kk = mt*16 + g;
            *(float2*)(g_delta + dbase + (size_t)kk*64 + dd)
                = make_float2(da[nt][0], da[nt][1]);
            *(float2*)(g_delta + dbase + (size_t)(kk+8)*64 + dd)
                = make_float2(da[nt][2], da[nt][3]);
        }
    }
}

// ---------------- kernel 4: state recurrence ----------------
__global__ __launch_bounds__(256) void recur_kernel(float* __restrict__ state_out)
{
    const int bh = blockIdx.x;
    const int b = bh >> 4, h = bh & 15;
    const int tid = threadIdx.x;
    float s[16];
    #pragma unroll
    for (int e = 0; e < 16; e++) s[e] = 0.0f;
    #pragma unroll 1
    for (int n = 0; n < NCH; n++) {
        const int cbid = (b * NCH + n) * HEADS + h;
        float asum = expf(g_m[cbid * CC + (CC - 1)]);
        size_t base = (size_t)cbid * 4096;
        #pragma unroll
        for (int e = 0; e < 16; e++) {
            int idx = tid + e * 256;
            g_stin[base + idx] = s[e];
            s[e] = s[e] * asum + g_delta[base + idx];
        }
    }
    size_t ob = (size_t)bh * 4096;
    #pragma unroll
    for (int e = 0; e < 16; e++) state_out[ob + tid + e * 256] = s[e];
}

// ---------------- kernel 5: y += (q @ state_in) * curve ----------------
__global__ __launch_bounds__(256) void ymem_kernel(float* __restrict__ y_out)
{
    __shared__ float qs[128*68];
    __shared__ float ss[64*68];
    __shared__ float cv[128];
    const int tid = threadIdx.x;
    const int bid = blockIdx.x;
    const int h = bid & 15;
    const int n = (bid >> 4) & 31;
    const int b = bid >> 9;
    const int tb = b * TLEN + n * CC;
    size_t sbase = (size_t)bid * 4096;

    #pragma unroll
    for (int it = 0; it < 8; it++) {
        int f = tid + it * 256;
        int c = f >> 4, d4 = (f & 15) << 2;
        *(float4*)(qs + c*68 + d4) =
            *(const float4*)(g_q + (tb + c) * DIMM + h * HD + d4);
    }
    #pragma unroll
    for (int it = 0; it < 4; it++) {
        int f = tid + it * 256;
        int kk = f >> 4, d4 = (f & 15) << 2;
        *(float4*)(ss + kk*68 + d4) = *(const float4*)(g_stin + sbase + kk*64 + d4);
    }
    if (tid < 128) cv[tid] = expf(g_m[bid * CC + tid]);
    __syncthreads();

    const int tx = tid & 7, ty = tid >> 3;
    const int c0 = ty * 4, dd0 = tx * 8;
    float a0[8], a1[8], a2[8], a3[8];
    #pragma unroll
    for (int e = 0; e < 8; e++) { a0[e]=0.f; a1[e]=0.f; a2[e]=0.f; a3[e]=0.f; }
    #pragma unroll 4
    for (int kk = 0; kk < 64; kk++) {
        float q0 = qs[(c0+0)*68 + kk];
        float q1 = qs[(c0+1)*68 + kk];
        float q2 = qs[(c0+2)*68 + kk];
        float q3 = qs[(c0+3)*68 + kk];
        float sv[8];
        *(float4*)&sv[0] = *(const float4*)&ss[kk*68 + dd0];
        *(float4*)&sv[4] = *(const float4*)&ss[kk*68 + dd0 + 4];
        #pragma unroll
        for (int e = 0; e < 8; e++) {
            a0[e] = fmaf(q0, sv[e], a0[e]);
            a1[e] = fmaf(q1, sv[e], a1[e]);
            a2[e] = fmaf(q2, sv[e], a2[e]);
            a3[e] = fmaf(q3, sv[e], a3[e]);
        }
    }
    #pragma unroll
    for (int i = 0; i < 4; i++) {
        float* ap = (i==0)?a0:(i==1)?a1:(i==2)?a2:a3;
        float cc = cv[c0 + i];
        size_t off = (size_t)(tb + c0 + i) * DIMM + h * HD + dd0;
        float4 o0 = *(float4*)(y_out + off);
        float4 o1 = *(float4*)(y_out + off + 4);
        o0.x += ap[0]*cc; o0.y += ap[1]*cc; o0.z += ap[2]*cc; o0.w += ap[3]*cc;
        o1.x += ap[4]*cc; o1.y += ap[5]*cc; o1.z += ap[6]*cc; o1.w += ap[7]*cc;
        *(float4*)(y_out + off)     = o0;
        *(float4*)(y_out + off + 4) = o1;
    }
}

// ---------------- launch ----------------
extern "C" void kernel_launch(void* const* d_in, const int* in_sizes, int n_in,
                              void* d_out, int out_size)
{
    (void)in_sizes; (void)n_in; (void)out_size;
    const float* x  = (const float*)d_in[0];
    const float* Wq = (const float*)d_in[1];
    const float* bq = (const float*)d_in[2];
    const float* Wk = (const float*)d_in[3];
    const float* bk = (const float*)d_in[4];
    const float* Wv = (const float*)d_in[5];
    const float* bv = (const float*)d_in[6];
    const float* Wb = (const float*)d_in[7];
    const float* bb = (const float*)d_in[8];
    const float* Wa = (const float*)d_in[9];
    const float* ba = (const float*)d_in[10];

    float* out       = (float*)d_out;
    float* y_out     = out;
    float* state_out = out + YN;
    float* alpha_out = out + YN + SN;

    cudaFuncSetAttribute(intra_kernel,
                         cudaFuncAttributeMaxDynamicSharedMemorySize, I_BYTES);
    cudaFuncSetAttribute(proj_mma_kernel,
                         cudaFuncAttributeMaxDynamicSharedMemorySize, PROJ_SMEM);

    conv_x_kernel<<<MTOT * DIMM / 4 / 256, 256>>>(x);
    conv_w_kernel<<<NOUT * DIMM / 4 / 256, 256>>>(Wq, Wk, Wv, Wb, Wa);
    dim3 g1(40, 128);
    proj_mma_kernel<<<g1, 256, PROJ_SMEM>>>(bq, bk, bv, bb, ba, alpha_out);
    stats_kernel<<<BSZ*NCH*HEADS, 128>>>();
    intra_kernel<<<BSZ*NCH*HEADS, 256, I_BYTES>>>(y_out);
    recur_kernel<<<BSZ*HEADS, 256>>>(state_out);
    ymem_kernel<<<BSZ*NCH*HEADS, 256>>>(y_out);
}

// round 15
// speedup vs baseline: 1.3857x; 1.1543x over previous
#include <cuda_runtime.h>
#include <cuda_bf16.h>
#include <cuda_fp16.h>
#include <math.h>
#include <stdint.h>

#define DIMM   1024
#define HEADS  16
#define HD     64
#define CC     128
#define BSZ    4
#define TLEN   4096
#define NCH    (TLEN/CC)        /* 32 */
#define MTOT   (BSZ*TLEN)       /* 16384 */
#define KX     1024             /* uniform fp16 K for all 5 projections */
#define NOUT   5120

#define YN  (MTOT*DIMM)
#define SN  (BSZ*HEADS*HD*HD)

// ---------------- scratch ----------------
__device__ float g_q [MTOT*DIMM];
__device__ float g_bt[MTOT*DIMM];
__device__ float g_la[MTOT*DIMM];
__device__ __half g_qh[MTOT*DIMM];
__device__ __half g_kh[MTOT*DIMM];
__device__ __half g_vh[MTOT*DIMM];
__device__ __half g_bh[MTOT*DIMM];
__device__ float g_m [BSZ*NCH*HEADS*CC];
__device__ float g_bm[BSZ*NCH*HEADS*CC];
__device__ __half g_x2[(size_t)MTOT*KX];    // x in fp16 (hi)
__device__ __half g_w2[(size_t)NOUT*KX];    // all 5 W in fp16 (hi)
__device__ float g_delta[(size_t)BSZ*NCH*HEADS*HD*HD];
__device__ float g_stin [(size_t)BSZ*NCH*HEADS*HD*HD];

__device__ __forceinline__ float softplusf(float x) {
    return fmaxf(x, 0.0f) + log1pf(expf(-fabsf(x)));
}
__device__ __forceinline__ uint32_t s2u(const void* p) {
    uint32_t a;
    asm("{ .reg .u64 t; cvta.to.shared.u64 t, %1; cvt.u32.u64 %0, t; }"
        : "=r"(a) : "l"(p));
    return a;
}
__device__ __forceinline__ uint32_t f22h(float a, float b) {
    __half2 h = __floats2half2_rn(a, b);
    return *(uint32_t*)&h;
}
#define CP16(dst,src) asm volatile("cp.async.cg.shared.global [%0], [%1], 16;" ::"r"(dst),"l"(src):"memory")
#define CP_COMMIT()   asm volatile("cp.async.commit_group;" :::"memory")
#define CP_WAITN(n)   asm volatile("cp.async.wait_group %0;" ::"n"(n):"memory")

#define LDM_X4(r0,r1,r2,r3,addr) \
    asm volatile("ldmatrix.sync.aligned.m8n8.x4.shared.b16 {%0,%1,%2,%3}, [%4];" \
        : "=r"(r0),"=r"(r1),"=r"(r2),"=r"(r3) : "r"(addr))

#define LDM_X4T(r0,r1,r2,r3,addr) \
    asm volatile("ldmatrix.sync.aligned.m8n8.x4.trans.shared.b16 {%0,%1,%2,%3}, [%4];" \
        : "=r"(r0),"=r"(r1),"=r"(r2),"=r"(r3) : "r"(addr))

#define MMA16816(d0,d1,d2,d3,a0,a1,a2,a3,b0,b1) \
    asm volatile("mma.sync.aligned.m16n8k16.row.col.f32.f16.f16.f32 " \
        "{%0,%1,%2,%3}, {%4,%5,%6,%7}, {%8,%9}, {%0,%1,%2,%3};" \
        : "+f"(d0),"+f"(d1),"+f"(d2),"+f"(d3) \
        : "r"(a0),"r"(a1),"r"(a2),"r"(a3),"r"(b0),"r"(b1))

// ---------------- conversion kernels ----------------
__global__ __launch_bounds__(256) void conv_x_kernel(const float* __restrict__ x)
{
    size_t i4 = (size_t)blockIdx.x * 256 + threadIdx.x;
    float4 v = ((const float4*)x)[i4];
    __half h[4];
    h[0] = __float2half_rn(v.x); h[1] = __float2half_rn(v.y);
    h[2] = __float2half_rn(v.z); h[3] = __float2half_rn(v.w);
    *(uint2*)(g_x2 + i4 * 4) = *(uint2*)h;
}

__global__ __launch_bounds__(256) void conv_w_kernel(
    const float* __restrict__ W0, const float* __restrict__ W1,
    const float* __restrict__ W2, const float* __restrict__ W3,
    const float* __restrict__ W4)
{
    size_t i4 = (size_t)blockIdx.x * 256 + threadIdx.x;
    size_t n = i4 >> 8;
    int k4 = (int)(i4 & 255);
    int wsel = (int)(n >> 10);
    const float* W = (wsel == 0) ? W0 : (wsel == 1) ? W1 : (wsel == 2) ? W2
                   : (wsel == 3) ? W3 : W4;
    float4 v = ((const float4*)(W + (n & 1023) * DIMM))[k4];
    __half h[4];
    h[0] = __float2half_rn(v.x); h[1] = __float2half_rn(v.y);
    h[2] = __float2half_rn(v.z); h[3] = __float2half_rn(v.w);
    *(uint2*)(g_w2 + n * KX + k4 * 4) = *(uint2*)h;
}

// ---------------- kernel 1: mma.sync fp16 projection GEMM ----------------
// All 5 projections: K=1024 fp16 (uniform). 128x128 tile, BK=32, 4-stage
// cp.async, 8 warps (2m x 4n), warp tile 64x32.
#define BK     32
#define NKIT   (KX/BK)               /* 32 */
#define LDS_ROW 80
#define ATILE_B (128*LDS_ROW)
#define STG_B   (2*ATILE_B)
#define NSTG   4
#define PROJ_SMEM (NSTG*STG_B)       /* 81920 */

__global__ __launch_bounds__(256, 2) void proj_mma_kernel(
    const float* __restrict__ bq, const float* __restrict__ bk,
    const float* __restrict__ bv, const float* __restrict__ bb,
    const float* __restrict__ ba, float* __restrict__ alpha_out)
{
    extern __shared__ char dsm[];
    __shared__ float bias_s[128];
    const uint32_t sbase = s2u(dsm);
    const int tid = threadIdx.x;
    const int wid = tid >> 5, lane = tid & 31;
    const int nb = blockIdx.x, mb = blockIdx.y;
    const int wi = nb >> 3;
    const int m0 = mb * 128;
    const int r0g = nb * 128;
    const int r0  = (nb & 7) * 128;

    const float* bias = (wi == 0) ? bq : (wi == 1) ? bk : (wi == 2) ? bv
                       : (wi == 3) ? bb : ba;
    if (tid < 128) bias_s[tid] = bias[r0 + tid];

    int ch0 = tid * 2;
    int arow0 = ch0 >> 2,        ac0 = (ch0 & 3);
    int arow1 = (ch0+1) >> 2,    ac1 = ((ch0+1) & 3);
    const char* aG0 = (const char*)(g_x2 + (size_t)(m0 + arow0) * KX) + ac0 * 16;
    const char* aG1 = (const char*)(g_x2 + (size_t)(m0 + arow1) * KX) + ac1 * 16;
    const char* bG0 = (const char*)(g_w2 + (size_t)(r0g + arow0) * KX) + ac0 * 16;
    const char* bG1 = (const char*)(g_w2 + (size_t)(r0g + arow1) * KX) + ac1 * 16;
    uint32_t aD0 = arow0 * LDS_ROW + ac0 * 16;
    uint32_t aD1 = arow1 * LDS_ROW + ac1 * 16;

    #define LOAD_STAGE(s, kit) do {                                     \
        uint32_t st = sbase + (s) * STG_B;                              \
        size_t kb = (size_t)(kit) * (BK * 2);                           \
        CP16(st + aD0,           aG0 + kb);                             \
        CP16(st + aD1,           aG1 + kb);                             \
        CP16(st + ATILE_B + aD0, bG0 + kb);                             \
        CP16(st + ATILE_B + aD1, bG1 + kb);                             \
        CP_COMMIT();                                                    \
    } while (0)

    const int warp_m = wid >> 2;
    const int warp_n = wid & 3;
    const int lr = lane & 15, lh = lane >> 4;
    const uint32_t aOff = (uint32_t)(warp_m * 64 + lr) * LDS_ROW + lh * 16;
    const uint32_t bOff = (uint32_t)(warp_n * 32 + lr) * LDS_ROW + lh * 16 + ATILE_B;

    float acc[4][4][4];
    #pragma unroll
    for (int i = 0; i < 4; i++)
        #pragma unroll
        for (int j = 0; j < 4; j++)
            #pragma unroll
            for (int e = 0; e < 4; e++) acc[i][j][e] = 0.0f;

    LOAD_STAGE(0, 0);
    LOAD_STAGE(1, 1);
    LOAD_STAGE(2, 2);
    __syncthreads();

    #pragma unroll 1
    for (int i = 0; i < NKIT; i++) {
        if      (i + 2 < NKIT) CP_WAITN(2);
        else if (i + 1 < NKIT) CP_WAITN(1);
        else                   CP_WAITN(0);
        __syncthreads();
        if (i + 3 < NKIT) LOAD_STAGE((i + 3) % NSTG, i + 3);

        const uint32_t st = sbase + (i % NSTG) * STG_B;
        #pragma unroll
        for (int ks = 0; ks < 2; ks++) {
            uint32_t af[4][4];
            #pragma unroll
            for (int mf = 0; mf < 4; mf++)
                LDM_X4(af[mf][0], af[mf][1], af[mf][2], af[mf][3],
                       st + aOff + mf * (16 * LDS_ROW) + ks * 32);
            uint32_t bf[2][4];
            #pragma unroll
            for (int nf = 0; nf < 2; nf++)
                LDM_X4(bf[nf][0], bf[nf][1], bf[nf][2], bf[nf][3],
                       st + bOff + nf * (16 * LDS_ROW) + ks * 32);
            #pragma unroll
            for (int mf = 0; mf < 4; mf++) {
                #pragma unroll
                for (int nf = 0; nf < 2; nf++) {
                    MMA16816(acc[mf][nf*2][0], acc[mf][nf*2][1],
                             acc[mf][nf*2][2], acc[mf][nf*2][3],
                             af[mf][0], af[mf][1], af[mf][2], af[mf][3],
                             bf[nf][0], bf[nf][2]);
                    MMA16816(acc[mf][nf*2+1][0], acc[mf][nf*2+1][1],
                             acc[mf][nf*2+1][2], acc[mf][nf*2+1][3],
                             af[mf][0], af[mf][1], af[mf][2], af[mf][3],
                             bf[nf][1], bf[nf][3]);
                }
            }
        }
    }

    const int g = lane >> 2, t4 = lane & 3;
    const int mBase = m0 + warp_m * 64;
    #pragma unroll
    for (int mf = 0; mf < 4; mf++) {
        #pragma unroll
        for (int nf = 0; nf < 4; nf++) {
            int nl = warp_n * 32 + nf * 8 + t4 * 2;
            float b0 = bias_s[nl], b1 = bias_s[nl + 1];
            #pragma unroll
            for (int half = 0; half < 2; half++) {
                int m = mBase + mf * 16 + g + half * 8;
                float v0 = acc[mf][nf][half*2 + 0] + b0;
                float v1 = acc[mf][nf][half*2 + 1] + b1;
                size_t off = (size_t)m * DIMM + r0 + nl;
                if (wi == 0) {
                    float s0 = v0 * 0.125f, s1 = v1 * 0.125f;
                    *(float2*)(g_q + off) = make_float2(s0, s1);
                    *(uint32_t*)(g_qh + off) = f22h(s0, s1);
                } else if (wi == 1) {
                    *(uint32_t*)(g_kh + off) = f22h(v0 * 0.125f, v1 * 0.125f);
                } else if (wi == 2) {
                    *(uint32_t*)(g_vh + off) = f22h(v0, v1);
                } else if (wi == 3) {
                    float s0 = softplusf(v0), s1 = softplusf(v1);
                    *(float2*)(g_bt + off) = make_float2(s0, s1);
                    *(uint32_t*)(g_bh + off) = f22h(s0, s1);
                } else {
                    float z0 = fminf(10.0f, fmaxf(-10.0f, v0));
                    float z1 = fminf(10.0f, fmaxf(-10.0f, v1));
                    *(float2*)(alpha_out + off) =
                        make_float2(1.0f/(1.0f+expf(-z0)), 1.0f/(1.0f+expf(-z1)));
                    *(float2*)(g_la + off) =
                        make_float2(-softplusf(-z0), -softplusf(-z1));
                }
            }
        }
    }
}

// ---------------- kernel 2: per-chunk stats ----------------
__global__ __launch_bounds__(128) void stats_kernel()
{
    const int bid = blockIdx.x;
    const int c = threadIdx.x;
    const int h = bid & 15;
    const int n = (bid >> 4) & 31;
    const int b = bid >> 9;
    const int t = b * TLEN + n * CC + c;
    const int base = t * DIMM + h * HD;
    float sla = 0.0f, sb = 0.0f;
    #pragma unroll
    for (int d4 = 0; d4 < HD; d4 += 4) {
        float4 u = *(const float4*)(g_la + base + d4);
        float4 w = *(const float4*)(g_bt + base + d4);
        sla += u.x + u.y + u.z + u.w;
        sb  += w.x + w.y + w.z + w.w;
    }
    g_bm[bid * CC + c] = sb * (1.0f/64.0f);
    __shared__ float smem[CC];
    smem[c] = sla * (1.0f/64.0f);
    __syncthreads();
    #pragma unroll
    for (int off = 1; off < CC; off <<= 1) {
        float prev = (c >= off) ? smem[c - off] : 0.0f;
        __syncthreads();
        smem[c] += prev;
        __syncthreads();
    }
    g_m[bid * CC + c] = smem[c];
}

// ---------------- kernel 3: intra-chunk attention + delta (fp16 mma) ----------------
#define I_QS   0
#define I_KS   (128*72)
#define I_VBT  (2*128*72)
#define I_VBMT (2*128*72 + 64*136)
#define I_HALVES (2*128*72 + 2*64*136)
#define I_BYTES (I_HALVES*2 + 128*4)     /* 72192 */

__global__ __launch_bounds__(256, 1) void intra_kernel(float* __restrict__ y_out)
{
    extern __shared__ __half smh[];
    __half* qs   = smh + I_QS;
    __half* ks   = smh + I_KS;
    __half* vbT  = smh + I_VBT;
    __half* vbmT = smh + I_VBMT;
    float*  ms   = (float*)(smh + I_HALVES);
    const uint32_t qsU = s2u(qs), ksU = s2u(ks);
    const uint32_t vbTU = s2u(vbT), vbmTU = s2u(vbmT);

    const int tid = threadIdx.x;
    const int bid = blockIdx.x;
    const int h = bid & 15;
    const int n = (bid >> 4) & 31;
    const int b = bid >> 9;
    const int tbase = b * TLEN + n * CC;

    #pragma unroll
    for (int it = 0; it < 8; it++) {
        int f  = tid + it * 256;
        int c  = f >> 4;
        int d4 = (f & 15) << 2;
        size_t gi = (size_t)(tbase + c) * DIMM + h * HD + d4;
        *(uint2*)(qs + c*72 + d4) = *(const uint2*)(g_qh + gi);
        *(uint2*)(ks + c*72 + d4) = *(const uint2*)(g_kh + gi);
        uint2 vv = *(const uint2*)(g_vh + gi);
        uint2 bv = *(const uint2*)(g_bh + gi);
        const __half* vh = (const __half*)&vv;
        const __half* bh = (const __half*)&bv;
        float bm = g_bm[bid * CC + c];
        #pragma unroll
        for (int e = 0; e < 4; e++) {
            float vf = __half2float(vh[e]);
            vbT [(d4+e)*136 + c] = __float2half_rn(vf * __half2float(bh[e]));
            vbmT[(d4+e)*136 + c] = __float2half_rn(vf * bm);
        }
    }
    if (tid < 128) ms[tid] = g_m[bid * CC + tid];
    __syncthreads();

    const int w = tid >> 5, lane = tid & 31;
    const int g = lane >> 2, t4 = lane & 3;
    const int lr = lane & 15, lh = lane >> 4;
    const int i0 = w * 16;

    float sacc[16][4];
    #pragma unroll
    for (int j = 0; j < 16; j++)
        #pragma unroll
        for (int e = 0; e < 4; e++) sacc[j][e] = 0.0f;

    #pragma unroll
    for (int ka = 0; ka < 4; ka++) {
        uint32_t a0,a1,a2,a3;
        LDM_X4(a0,a1,a2,a3, qsU + (uint32_t)(i0 + lr)*144 + lh*16 + ka*32);
        #pragma unroll
        for (int jp = 0; jp < 8; jp++) {
            if (jp <= w) {
                uint32_t b0,b1,b2,b3;
                LDM_X4(b0,b1,b2,b3, ksU + (uint32_t)(jp*16 + lr)*144 + lh*16 + ka*32);
                MMA16816(sacc[2*jp][0], sacc[2*jp][1], sacc[2*jp][2], sacc[2*jp][3],
                         a0,a1,a2,a3, b0,b2);
                MMA16816(sacc[2*jp+1][0], sacc[2*jp+1][1], sacc[2*jp+1][2], sacc[2*jp+1][3],
                         a0,a1,a2,a3, b1,b3);
            }
        }
    }

    {
        float mi0 = ms[i0 + g], mi1 = ms[i0 + g + 8];
        int r0 = i0 + g, r1 = i0 + g + 8;
        #pragma unroll
        for (int j = 0; j < 16; j++) {
            if (j <= 2*w + 1) {
                int c0 = j*8 + t4*2, c1 = c0 + 1;
                float mj0 = ms[c0], mj1 = ms[c1];
                sacc[j][0] = (c0 <= r0) ? sacc[j][0] * expf(mi0 - mj0) : 0.0f;
                sacc[j][1] = (c1 <= r0) ? sacc[j][1] * expf(mi0 - mj1) : 0.0f;
                sacc[j][2] = (c0 <= r1) ? sacc[j][2] * expf(mi1 - mj0) : 0.0f;
                sacc[j][3] = (c1 <= r1) ? sacc[j][3] * expf(mi1 - mj1) : 0.0f;
            }
        }
    }

    uint32_t ha[8][4];
    #pragma unroll
    for (int k2 = 0; k2 < 8; k2++) {
        if (k2 <= w) {
            ha[k2][0] = f22h(sacc[2*k2][0],   sacc[2*k2][1]);
            ha[k2][1] = f22h(sacc[2*k2][2],   sacc[2*k2][3]);
            ha[k2][2] = f22h(sacc[2*k2+1][0], sacc[2*k2+1][1]);
            ha[k2][3] = f22h(sacc[2*k2+1][2], sacc[2*k2+1][3]);
        }
    }

    float ya[8][4];
    #pragma unroll
    for (int j = 0; j < 8; j++)
        #pragma unroll
        for (int e = 0; e < 4; e++) ya[j][e] = 0.0f;

    #pragma unroll
    for (int k2 = 0; k2 < 8; k2++) {
        if (k2 <= w) {
            #pragma unroll
            for (int np = 0; np < 4; np++) {
                uint32_t b0,b1,b2,b3;
                LDM_X4(b0,b1,b2,b3, vbTU + (uint32_t)(np*16 + lr)*272 + lh*16 + k2*32);
                MMA16816(ya[2*np][0], ya[2*np][1], ya[2*np][2], ya[2*np][3],
                         ha[k2][0], ha[k2][1], ha[k2][2], ha[k2][3], b0, b2);
                MMA16816(ya[2*np+1][0], ya[2*np+1][1], ya[2*np+1][2], ya[2*np+1][3],
                         ha[k2][0], ha[k2][1], ha[k2][2], ha[k2][3], b1, b3);
            }
        }
    }
    #pragma unroll
    for (int nt = 0; nt < 8; nt++) {
        int dd = nt*8 + t4*2;
        size_t o0 = (size_t)(tbase + i0 + g) * DIMM + h * HD + dd;
        *(float2*)(y_out + o0)            = make_float2(ya[nt][0], ya[nt][1]);
        *(float2*)(y_out + o0 + 8*DIMM)   = make_float2(ya[nt][2], ya[nt][3]);
    }

    {
        const int mt = w >> 1;
        const int nh = w & 1;
        float da[4][4];
        #pragma unroll
        for (int j = 0; j < 4; j++)
            #pragma unroll
            for (int e = 0; e < 4; e++) da[j][e] = 0.0f;

        const int lg = lane >> 3, li = lane & 7;
        const int rowc_off = li + ((lg >> 1) & 1) * 8;
        const int colf = mt*16 + (lg & 1) * 8;
        #pragma unroll
        for (int ka = 0; ka < 8; ka++) {
            uint32_t a0,a1,a2,a3;
            LDM_X4T(a0,a1,a2,a3,
                    ksU + (uint32_t)(ka*16 + rowc_off)*144 + colf*2);
            #pragma unroll
            for (int np = 0; np < 2; np++) {
                uint32_t b0,b1,b2,b3;
                LDM_X4(b0,b1,b2,b3,
                       vbmTU + (uint32_t)(nh*32 + np*16 + lr)*272 + lh*16 + ka*32);
                MMA16816(da[2*np][0], da[2*np][1], da[2*np][2], da[2*np][3],
                         a0,a1,a2,a3, b0,b2);
                MMA16816(da[2*np+1][0], da[2*np+1][1], da[2*np+1][2], da[2*np+1][3],
                         a0,a1,a2,a3, b1,b3);
            }
        }
        size_t dbase = (size_t)bid * 4096;
        #pragma unroll
        for (int nt = 0; nt < 4; nt++) {
            int dd = nh*32 + nt*8 + t4*2;
            int kk = mt*16 + g;
            *(float2*)(g_delta + dbase + (size_t)kk*64 + dd)
                = make_float2(da[nt][0], da[nt][1]);
            *(float2*)(g_delta + dbase + (size_t)(kk+8)*64 + dd)
                = make_float2(da[nt][2], da[nt][3]);
        }
    }
}

// ---------------- kernel 4: state recurrence ----------------
__global__ __launch_bounds__(256) void recur_kernel(float* __restrict__ state_out)
{
    const int bh = blockIdx.x;
    const int b = bh >> 4, h = bh & 15;
    const int tid = threadIdx.x;
    float s[16];
    #pragma unroll
    for (int e = 0; e < 16; e++) s[e] = 0.0f;
    #pragma unroll 1
    for (int n = 0; n < NCH; n++) {
        const int cbid = (b * NCH + n) * HEADS + h;
        float asum = expf(g_m[cbid * CC + (CC - 1)]);
        size_t base = (size_t)cbid * 4096;
        #pragma unroll
        for (int e = 0; e < 16; e++) {
            int idx = tid + e * 256;
            g_stin[base + idx] = s[e];
            s[e] = s[e] * asum + g_delta[base + idx];
        }
    }
    size_t ob = (size_t)bh * 4096;
    #pragma unroll
    for (int e = 0; e < 16; e++) state_out[ob + tid + e * 256] = s[e];
}

// ---------------- kernel 5: y += (q @ state_in) * curve ----------------
__global__ __launch_bounds__(256) void ymem_kernel(float* __restrict__ y_out)
{
    __shared__ float qs[128*68];
    __shared__ float ss[64*68];
    __shared__ float cv[128];
    const int tid = threadIdx.x;
    const int bid = blockIdx.x;
    const int h = bid & 15;
    const int n = (bid >> 4) & 31;
    const int b = bid >> 9;
    const int tb = b * TLEN + n * CC;
    size_t sbase = (size_t)bid * 4096;

    #pragma unroll
    for (int it = 0; it < 8; it++) {
        int f = tid + it * 256;
        int c = f >> 4, d4 = (f & 15) << 2;
        *(float4*)(qs + c*68 + d4) =
            *(const float4*)(g_q + (tb + c) * DIMM + h * HD + d4);
    }
    #pragma unroll
    for (int it = 0; it < 4; it++) {
        int f = tid + it * 256;
        int kk = f >> 4, d4 = (f & 15) << 2;
        *(float4*)(ss + kk*68 + d4) = *(const float4*)(g_stin + sbase + kk*64 + d4);
    }
    if (tid < 128) cv[tid] = expf(g_m[bid * CC + tid]);
    __syncthreads();

    const int tx = tid & 7, ty = tid >> 3;
    const int c0 = ty * 4, dd0 = tx * 8;
    float a0[8], a1[8], a2[8], a3[8];
    #pragma unroll
    for (int e = 0; e < 8; e++) { a0[e]=0.f; a1[e]=0.f; a2[e]=0.f; a3[e]=0.f; }
    #pragma unroll 4
    for (int kk = 0; kk < 64; kk++) {
        float q0 = qs[(c0+0)*68 + kk];
        float q1 = qs[(c0+1)*68 + kk];
        float q2 = qs[(c0+2)*68 + kk];
        float q3 = qs[(c0+3)*68 + kk];
        float sv[8];
        *(float4*)&sv[0] = *(const float4*)&ss[kk*68 + dd0];
        *(float4*)&sv[4] = *(const float4*)&ss[kk*68 + dd0 + 4];
        #pragma unroll
        for (int e = 0; e < 8; e++) {
            a0[e] = fmaf(q0, sv[e], a0[e]);
            a1[e] = fmaf(q1, sv[e], a1[e]);
            a2[e] = fmaf(q2, sv[e], a2[e]);
            a3[e] = fmaf(q3, sv[e], a3[e]);
        }
    }
    #pragma unroll
    for (int i = 0; i < 4; i++) {
        float* ap = (i==0)?a0:(i==1)?a1:(i==2)?a2:a3;
        float cc = cv[c0 + i];
        size_t off = (size_t)(tb + c0 + i) * DIMM + h * HD + dd0;
        float4 o0 = *(float4*)(y_out + off);
        float4 o1 = *(float4*)(y_out + off + 4);
        o0.x += ap[0]*cc; o0.y += ap[1]*cc; o0.z += ap[2]*cc; o0.w += ap[3]*cc;
        o1.x += ap[4]*cc; o1.y += ap[5]*cc; o1.z += ap[6]*cc; o1.w += ap[7]*cc;
        *(float4*)(y_out + off)     = o0;
        *(float4*)(y_out + off + 4) = o1;
    }
}

// ---------------- launch ----------------
extern "C" void kernel_launch(void* const* d_in, const int* in_sizes, int n_in,
                              void* d_out, int out_size)
{
    (void)in_sizes; (void)n_in; (void)out_size;
    const float* x  = (const float*)d_in[0];
    const float* Wq = (const float*)d_in[1];
    const float* bq = (const float*)d_in[2];
    const float* Wk = (const float*)d_in[3];
    const float* bk = (const float*)d_in[4];
    const float* Wv = (const float*)d_in[5];
    const float* bv = (const float*)d_in[6];
    const float* Wb = (const float*)d_in[7];
    const float* bb = (const float*)d_in[8];
    const float* Wa = (const float*)d_in[9];
    const float* ba = (const float*)d_in[10];

    float* out       = (float*)d_out;
    float* y_out     = out;
    float* state_out = out + YN;
    float* alpha_out = out + YN + SN;

    cudaFuncSetAttribute(intra_kernel,
                         cudaFuncAttributeMaxDynamicSharedMemorySize, I_BYTES);
    cudaFuncSetAttribute(proj_mma_kernel,
                         cudaFuncAttributeMaxDynamicSharedMemorySize, PROJ_SMEM);

    conv_x_kernel<<<MTOT * DIMM / 4 / 256, 256>>>(x);
    conv_w_kernel<<<NOUT * DIMM / 4 / 256, 256>>>(Wq, Wk, Wv, Wb, Wa);
    dim3 g1(40, 128);
    proj_mma_kernel<<<g1, 256, PROJ_SMEM>>>(bq, bk, bv, bb, ba, alpha_out);
    stats_kernel<<<BSZ*NCH*HEADS, 128>>>();
    intra_kernel<<<BSZ*NCH*HEADS, 256, I_BYTES>>>(y_out);
    recur_kernel<<<BSZ*HEADS, 256>>>(state_out);
    ymem_kernel<<<BSZ*NCH*HEADS, 256>>>(y_out);
}